// round 1
// baseline (speedup 1.0000x reference)
#include <cuda_runtime.h>
#include <math.h>

#define T_TOK 512
#define N_RES 4096
#define C_DIM 384
#define H_HEADS 8
#define KD 48
#define F_DIM 1536
#define LN_EPS 1e-5f
#define BIGF 1e9f

// ---------------- scratch (device globals; no runtime alloc allowed) ----------------
__device__ float g_qin [T_TOK * C_DIM];
__device__ float g_din [N_RES * C_DIM];
__device__ float g_ln4 [N_RES * C_DIM];
__device__ float g_q   [T_TOK * C_DIM];
__device__ float g_gate[T_TOK * C_DIM];
__device__ float g_k   [N_RES * C_DIM];
__device__ float g_v   [N_RES * C_DIM];
__device__ float g_logits[(size_t)H_HEADS * T_TOK * N_RES];   // 67 MB
__device__ float g_wag [T_TOK * C_DIM];
__device__ float g_ln3 [T_TOK * C_DIM];
__device__ float g_h1  [T_TOK * F_DIM];
__device__ float g_h2  [N_RES * F_DIM];

// ---------------- LayerNorm: one block (128 thr) per row of 384 ----------------
__global__ void ln_kernel(const float* __restrict__ x, const float* __restrict__ scale,
                          const float* __restrict__ offset, float* __restrict__ out) {
    int row = blockIdx.x;
    const float* xr = x + (size_t)row * C_DIM;
    int t = threadIdx.x;
    float v0 = xr[t], v1 = xr[t + 128], v2 = xr[t + 256];
    float s  = v0 + v1 + v2;
    float s2 = v0 * v0 + v1 * v1 + v2 * v2;
    #pragma unroll
    for (int o = 16; o; o >>= 1) {
        s  += __shfl_down_sync(0xffffffffu, s,  o);
        s2 += __shfl_down_sync(0xffffffffu, s2, o);
    }
    __shared__ float sh[8];
    __shared__ float mu_s, rstd_s;
    int wid = t >> 5, lane = t & 31;
    if (lane == 0) { sh[wid] = s; sh[4 + wid] = s2; }
    __syncthreads();
    if (t == 0) {
        float ts  = sh[0] + sh[1] + sh[2] + sh[3];
        float ts2 = sh[4] + sh[5] + sh[6] + sh[7];
        float mu  = ts * (1.0f / C_DIM);
        float var = ts2 * (1.0f / C_DIM) - mu * mu;
        mu_s = mu; rstd_s = rsqrtf(var + LN_EPS);
    }
    __syncthreads();
    float mu = mu_s, rstd = rstd_s;
    float* orow = out + (size_t)row * C_DIM;
    orow[t]       = scale[t]       * (v0 - mu) * rstd + offset[t];
    orow[t + 128] = scale[t + 128] * (v1 - mu) * rstd + offset[t + 128];
    orow[t + 256] = scale[t + 256] * (v2 - mu) * rstd + offset[t + 256];
}

// ---------------- generic tiled fp32 GEMM, 64x64x16, 4x4 micro-tile ----------------
// C[M,N] = act(alpha * A@B + bias) + residual   (all row-major, dims multiples of 64/16)
#define ACT_NONE 0
#define ACT_RELU 1
#define ACT_SIGMOID 2

__global__ __launch_bounds__(256) void gemm64(
    const float* __restrict__ A, const float* __restrict__ B, float* __restrict__ C,
    int M, int N, int K, float alpha,
    const float* __restrict__ bias, int act, const float* __restrict__ residual) {
    __shared__ float As[16][64];
    __shared__ float Bs[16][64];
    int t  = threadIdx.x;
    int bm = blockIdx.y * 64, bn = blockIdx.x * 64;
    int tx = t & 15, ty = t >> 4;
    float acc[4][4] = {};
    for (int k0 = 0; k0 < K; k0 += 16) {
        #pragma unroll
        for (int i = 0; i < 4; i++) {
            int lin = t + i * 256;
            int m = lin >> 4, kk = lin & 15;
            As[kk][m] = A[(size_t)(bm + m) * K + k0 + kk];
        }
        #pragma unroll
        for (int i = 0; i < 4; i++) {
            int lin = t + i * 256;
            int n = lin & 63, kk = lin >> 6;
            Bs[kk][n] = B[(size_t)(k0 + kk) * N + bn + n];
        }
        __syncthreads();
        #pragma unroll
        for (int kk = 0; kk < 16; kk++) {
            float4 a4 = *reinterpret_cast<const float4*>(&As[kk][ty * 4]);
            float4 b4 = *reinterpret_cast<const float4*>(&Bs[kk][tx * 4]);
            float a[4] = {a4.x, a4.y, a4.z, a4.w};
            float b[4] = {b4.x, b4.y, b4.z, b4.w};
            #pragma unroll
            for (int i = 0; i < 4; i++)
                #pragma unroll
                for (int j = 0; j < 4; j++)
                    acc[i][j] += a[i] * b[j];
        }
        __syncthreads();
    }
    #pragma unroll
    for (int i = 0; i < 4; i++) {
        int m = bm + ty * 4 + i;
        #pragma unroll
        for (int j = 0; j < 4; j++) {
            int n = bn + tx * 4 + j;
            float v = acc[i][j] * alpha;
            if (bias) v += bias[n];
            if (act == ACT_RELU)        v = fmaxf(v, 0.0f);
            else if (act == ACT_SIGMOID) v = 1.0f / (1.0f + __expf(-v));
            if (residual) v += residual[(size_t)m * N + n];
            C[(size_t)m * N + n] = v;
        }
    }
}

// ---------------- attention scores: logits[h,t,r] = q[t,h,:]·k[r,h,:] + BIG*(mask-1) ----------------
__global__ __launch_bounds__(256) void scores_kernel(
    const float* __restrict__ q, const float* __restrict__ k,
    const float* __restrict__ mask, float* __restrict__ logits) {
    int h  = blockIdx.z;
    int bt = blockIdx.y * 64, br = blockIdx.x * 64;
    __shared__ float Qs[KD][64];
    __shared__ float Ks[KD][64];
    int t = threadIdx.x;
    int tx = t & 15, ty = t >> 4;
    #pragma unroll
    for (int i = 0; i < 12; i++) {
        int lin = t + i * 256;               // 0..3071
        int m = lin / KD, c = lin % KD;
        Qs[c][m] = q[(size_t)(bt + m) * C_DIM + h * KD + c];
        Ks[c][m] = k[(size_t)(br + m) * C_DIM + h * KD + c];
    }
    __syncthreads();
    float acc[4][4] = {};
    #pragma unroll 4
    for (int c = 0; c < KD; c++) {
        float4 a4 = *reinterpret_cast<const float4*>(&Qs[c][ty * 4]);
        float4 b4 = *reinterpret_cast<const float4*>(&Ks[c][tx * 4]);
        float a[4] = {a4.x, a4.y, a4.z, a4.w};
        float b[4] = {b4.x, b4.y, b4.z, b4.w};
        #pragma unroll
        for (int i = 0; i < 4; i++)
            #pragma unroll
            for (int j = 0; j < 4; j++)
                acc[i][j] += a[i] * b[j];
    }
    #pragma unroll
    for (int i = 0; i < 4; i++) {
        int tt = bt + ty * 4 + i;
        #pragma unroll
        for (int j = 0; j < 4; j++) {
            int rr = br + tx * 4 + j;
            size_t idx = ((size_t)h * T_TOK + tt) * N_RES + rr;
            logits[idx] = acc[i][j] + BIGF * (mask[idx] - 1.0f);
        }
    }
}

// ---------------- row softmax over R=4096, in place ----------------
__global__ __launch_bounds__(256) void softmax_kernel(float* __restrict__ logits) {
    size_t row = blockIdx.x;
    float* lr = logits + row * N_RES;
    int t = threadIdx.x;
    float e[16];
    float m = -1e30f;
    #pragma unroll
    for (int i = 0; i < 16; i++) { e[i] = lr[t + i * 256]; m = fmaxf(m, e[i]); }
    __shared__ float sh[8];
    __shared__ float red_s;
    int wid = t >> 5, lane = t & 31;
    #pragma unroll
    for (int o = 16; o; o >>= 1) m = fmaxf(m, __shfl_down_sync(0xffffffffu, m, o));
    if (lane == 0) sh[wid] = m;
    __syncthreads();
    if (t == 0) {
        float mm = sh[0];
        #pragma unroll
        for (int w = 1; w < 8; w++) mm = fmaxf(mm, sh[w]);
        red_s = mm;
    }
    __syncthreads();
    m = red_s;
    float s = 0.0f;
    #pragma unroll
    for (int i = 0; i < 16; i++) { e[i] = __expf(e[i] - m); s += e[i]; }
    __syncthreads();
    #pragma unroll
    for (int o = 16; o; o >>= 1) s += __shfl_down_sync(0xffffffffu, s, o);
    if (lane == 0) sh[wid] = s;
    __syncthreads();
    if (t == 0) {
        float ss = 0.0f;
        #pragma unroll
        for (int w = 0; w < 8; w++) ss += sh[w];
        red_s = 1.0f / ss;
    }
    __syncthreads();
    float inv = red_s;
    #pragma unroll
    for (int i = 0; i < 16; i++) lr[t + i * 256] = e[i] * inv;
}

// ---------------- AV: wag[t, h*48+c] = gate * sum_r W[h,t,r] * v[r,h,c] ----------------
__global__ __launch_bounds__(256) void av_kernel(
    const float* __restrict__ w, const float* __restrict__ v,
    const float* __restrict__ gate, float* __restrict__ wag) {
    int h  = blockIdx.y;
    int bt = blockIdx.x * 64;
    __shared__ float Ws[64][65];   // [t][r]
    __shared__ float Vs[64][KD];   // [r][c]
    int t = threadIdx.x;
    int tx = t & 15, ty = t >> 4;  // tx -> 3 c's, ty -> 4 t's
    float acc[4][3] = {};
    for (int r0 = 0; r0 < N_RES; r0 += 64) {
        #pragma unroll
        for (int i = 0; i < 16; i++) {
            int lin = t + i * 256;
            int tt = lin >> 6, rr = lin & 63;
            Ws[tt][rr] = w[((size_t)h * T_TOK + bt + tt) * N_RES + r0 + rr];
        }
        #pragma unroll
        for (int i = 0; i < 12; i++) {
            int lin = t + i * 256;
            int rr = lin / KD, c = lin % KD;
            Vs[rr][c] = v[(size_t)(r0 + rr) * C_DIM + h * KD + c];
        }
        __syncthreads();
        #pragma unroll 4
        for (int rr = 0; rr < 64; rr++) {
            float a[4], b[3];
            #pragma unroll
            for (int i = 0; i < 4; i++) a[i] = Ws[ty * 4 + i][rr];
            #pragma unroll
            for (int j = 0; j < 3; j++) b[j] = Vs[rr][tx * 3 + j];
            #pragma unroll
            for (int i = 0; i < 4; i++)
                #pragma unroll
                for (int j = 0; j < 3; j++)
                    acc[i][j] += a[i] * b[j];
        }
        __syncthreads();
    }
    #pragma unroll
    for (int i = 0; i < 4; i++) {
        int tt = bt + ty * 4 + i;
        #pragma unroll
        for (int j = 0; j < 3; j++) {
            size_t idx = (size_t)tt * C_DIM + h * KD + tx * 3 + j;
            wag[idx] = acc[i][j] * gate[idx];
        }
    }
}

// ---------------- host launch ----------------
static float* sym(const void* s) {
    void* p = nullptr;
    cudaGetSymbolAddress(&p, s);
    return (float*)p;
}

extern "C" void kernel_launch(void* const* d_in, const int* in_sizes, int n_in,
                              void* d_out, int out_size) {
    const float* original   = (const float*)d_in[0];
    const float* resampled  = (const float*)d_in[1];
    const float* attn_mask  = (const float*)d_in[2];
    const float* qn_scale   = (const float*)d_in[5];
    const float* qn_offset  = (const float*)d_in[6];
    const float* dn_scale   = (const float*)d_in[7];
    const float* dn_offset  = (const float*)d_in[8];
    const float* query_w    = (const float*)d_in[9];
    const float* key_w      = (const float*)d_in[10];
    const float* value_w    = (const float*)d_in[11];
    const float* gating_w   = (const float*)d_in[12];
    const float* gating_b   = (const float*)d_in[13];
    const float* output_w   = (const float*)d_in[14];
    const float* output_b   = (const float*)d_in[15];
    const float* rt_ln_scale  = (const float*)d_in[16];
    const float* rt_ln_offset = (const float*)d_in[17];
    const float* rt_w1 = (const float*)d_in[18];
    const float* rt_b1 = (const float*)d_in[19];
    const float* rt_w2 = (const float*)d_in[20];
    const float* rt_b2 = (const float*)d_in[21];
    const float* ot_ln_scale  = (const float*)d_in[22];
    const float* ot_ln_offset = (const float*)d_in[23];
    const float* ot_w1 = (const float*)d_in[24];
    const float* ot_b1 = (const float*)d_in[25];
    const float* ot_w2 = (const float*)d_in[26];
    const float* ot_b2 = (const float*)d_in[27];

    float* out_res  = (float*)d_out;                       // [512, 384]
    float* out_orig = out_res + (size_t)T_TOK * C_DIM;     // [4096, 384]

    float* p_qin  = sym(g_qin);
    float* p_din  = sym(g_din);
    float* p_ln4  = sym(g_ln4);
    float* p_q    = sym(g_q);
    float* p_gate = sym(g_gate);
    float* p_k    = sym(g_k);
    float* p_v    = sym(g_v);
    float* p_log  = sym(g_logits);
    float* p_wag  = sym(g_wag);
    float* p_ln3  = sym(g_ln3);
    float* p_h1   = sym(g_h1);
    float* p_h2   = sym(g_h2);

    const float inv_sqrt_kd = 0.14433756729740643f;  // 1/sqrt(48)

    // LayerNorms on raw inputs
    ln_kernel<<<T_TOK, 128>>>(resampled, qn_scale, qn_offset, p_qin);
    ln_kernel<<<N_RES, 128>>>(original,  dn_scale, dn_offset, p_din);
    ln_kernel<<<N_RES, 128>>>(original,  ot_ln_scale, ot_ln_offset, p_ln4);

    // Projections
    gemm64<<<dim3(C_DIM / 64, T_TOK / 64), 256>>>(p_qin, query_w,  p_q,    T_TOK, C_DIM, C_DIM, inv_sqrt_kd, nullptr,  ACT_NONE,    nullptr);
    gemm64<<<dim3(C_DIM / 64, T_TOK / 64), 256>>>(p_qin, gating_w, p_gate, T_TOK, C_DIM, C_DIM, 1.0f,        gating_b, ACT_SIGMOID, nullptr);
    gemm64<<<dim3(C_DIM / 64, N_RES / 64), 256>>>(p_din, key_w,    p_k,    N_RES, C_DIM, C_DIM, 1.0f,        nullptr,  ACT_NONE,    nullptr);
    gemm64<<<dim3(C_DIM / 64, N_RES / 64), 256>>>(p_din, value_w,  p_v,    N_RES, C_DIM, C_DIM, 1.0f,        nullptr,  ACT_NONE,    nullptr);

    // Attention
    scores_kernel<<<dim3(N_RES / 64, T_TOK / 64, H_HEADS), 256>>>(p_q, p_k, attn_mask, p_log);
    softmax_kernel<<<H_HEADS * T_TOK, 256>>>(p_log);
    av_kernel<<<dim3(T_TOK / 64, H_HEADS), 256>>>(p_log, p_v, p_gate, p_wag);

    // Output projection + residual -> resampled2 (in d_out)
    gemm64<<<dim3(C_DIM / 64, T_TOK / 64), 256>>>(p_wag, output_w, out_res, T_TOK, C_DIM, C_DIM, 1.0f, output_b, ACT_NONE, resampled);

    // resampled transition
    ln_kernel<<<T_TOK, 128>>>(out_res, rt_ln_scale, rt_ln_offset, p_ln3);
    gemm64<<<dim3(F_DIM / 64, T_TOK / 64), 256>>>(p_ln3, rt_w1, p_h1,   T_TOK, F_DIM, C_DIM, 1.0f, rt_b1, ACT_RELU, nullptr);
    gemm64<<<dim3(C_DIM / 64, T_TOK / 64), 256>>>(p_h1,  rt_w2, out_res, T_TOK, C_DIM, F_DIM, 1.0f, rt_b2, ACT_NONE, out_res);

    // original transition
    gemm64<<<dim3(F_DIM / 64, N_RES / 64), 256>>>(p_ln4, ot_w1, p_h2,    N_RES, F_DIM, C_DIM, 1.0f, ot_b1, ACT_RELU, nullptr);
    gemm64<<<dim3(C_DIM / 64, N_RES / 64), 256>>>(p_h2,  ot_w2, out_orig, N_RES, C_DIM, F_DIM, 1.0f, ot_b2, ACT_NONE, original);
}

// round 2
// speedup vs baseline: 1.0879x; 1.0879x over previous
#include <cuda_runtime.h>
#include <math.h>

#define T_TOK 512
#define N_RES 4096
#define C_DIM 384
#define H_HEADS 8
#define KD 48
#define F_DIM 1536
#define LN_EPS 1e-5f
#define BIGF 1e9f

typedef unsigned long long ull;

// packed f32x2 helpers (sm_100+ PTX)
#define FMA_F32X2(d, a, b, c) \
    asm("fma.rn.f32x2 %0, %1, %2, %3;" : "=l"(d) : "l"(a), "l"(b), "l"(c))
#define PACK_DUP(out, x) \
    asm("mov.b64 %0, {%1, %1};" : "=l"(out) : "r"(__float_as_uint(x)))
#define UNPACK2(lo, hi, v) \
    asm("mov.b64 {%0, %1}, %2;" : "=r"(lo), "=r"(hi) : "l"(v))

// ---------------- scratch (device globals; no runtime alloc allowed) ----------------
__device__ float g_qin [T_TOK * C_DIM];
__device__ float g_din [N_RES * C_DIM];
__device__ float g_ln4 [N_RES * C_DIM];
__device__ float g_q   [T_TOK * C_DIM];
__device__ float g_gate[T_TOK * C_DIM];
__device__ float g_k   [N_RES * C_DIM];
__device__ float g_v   [N_RES * C_DIM];
__device__ float g_logits[(size_t)H_HEADS * T_TOK * N_RES];   // 67 MB
__device__ float g_wag [T_TOK * C_DIM];
__device__ float g_ln3 [T_TOK * C_DIM];
__device__ float g_h1  [T_TOK * F_DIM];
__device__ float g_h2  [N_RES * F_DIM];

// ---------------- LayerNorm: one block (128 thr) per row of 384 ----------------
__global__ void ln_kernel(const float* __restrict__ x, const float* __restrict__ scale,
                          const float* __restrict__ offset, float* __restrict__ out) {
    int row = blockIdx.x;
    const float* xr = x + (size_t)row * C_DIM;
    int t = threadIdx.x;
    float v0 = xr[t], v1 = xr[t + 128], v2 = xr[t + 256];
    float s  = v0 + v1 + v2;
    float s2 = v0 * v0 + v1 * v1 + v2 * v2;
    #pragma unroll
    for (int o = 16; o; o >>= 1) {
        s  += __shfl_down_sync(0xffffffffu, s,  o);
        s2 += __shfl_down_sync(0xffffffffu, s2, o);
    }
    __shared__ float sh[8];
    __shared__ float mu_s, rstd_s;
    int wid = t >> 5, lane = t & 31;
    if (lane == 0) { sh[wid] = s; sh[4 + wid] = s2; }
    __syncthreads();
    if (t == 0) {
        float ts  = sh[0] + sh[1] + sh[2] + sh[3];
        float ts2 = sh[4] + sh[5] + sh[6] + sh[7];
        float mu  = ts * (1.0f / C_DIM);
        float var = ts2 * (1.0f / C_DIM) - mu * mu;
        mu_s = mu; rstd_s = rsqrtf(var + LN_EPS);
    }
    __syncthreads();
    float mu = mu_s, rstd = rstd_s;
    float* orow = out + (size_t)row * C_DIM;
    orow[t]       = scale[t]       * (v0 - mu) * rstd + offset[t];
    orow[t + 128] = scale[t + 128] * (v1 - mu) * rstd + offset[t + 128];
    orow[t + 256] = scale[t + 256] * (v2 - mu) * rstd + offset[t + 256];
}

// ---------------- 128x128x8 double-buffered SGEMM with f32x2 packed FMA ----------------
// C[M,N] = act(alpha * A@B + bias) + residual   (row-major; M%128==0, N%128==0, K%8==0)
#define ACT_NONE 0
#define ACT_RELU 1
#define ACT_SIGMOID 2

__global__ __launch_bounds__(256, 2) void gemm128(
    const float* __restrict__ A, const float* __restrict__ B, float* __restrict__ C,
    int M, int N, int K, float alpha,
    const float* __restrict__ bias, int act, const float* __restrict__ residual) {
    __shared__ float As[2][8][128];
    __shared__ float Bs[2][8][128];
    int t  = threadIdx.x;
    int bm = blockIdx.y * 128, bn = blockIdx.x * 128;
    int tx = t & 15, ty = t >> 4;

    // global load mapping
    int ar = t >> 1;               // A row within tile (0..127)
    int ac = (t & 1) * 4;          // A col within k-tile (0 or 4)
    int br = t >> 5;               // B row within k-tile (0..7)
    int bc = (t & 31) * 4;         // B col within tile (0..124)

    const float* Aptr = A + (size_t)(bm + ar) * K + ac;
    const float* Bptr = B + (size_t)br * N + bn + bc;

    ull acc[8][4];
    ull zero; PACK_DUP(zero, 0.0f);
    #pragma unroll
    for (int i = 0; i < 8; i++)
        #pragma unroll
        for (int j = 0; j < 4; j++) acc[i][j] = zero;

    int kTiles = K >> 3;

    // prologue: load tile 0
    {
        float4 a4 = *reinterpret_cast<const float4*>(Aptr);
        float4 b4 = *reinterpret_cast<const float4*>(Bptr);
        As[0][ac + 0][ar] = a4.x; As[0][ac + 1][ar] = a4.y;
        As[0][ac + 2][ar] = a4.z; As[0][ac + 3][ar] = a4.w;
        *reinterpret_cast<float4*>(&Bs[0][br][bc]) = b4;
    }
    __syncthreads();

    for (int kt = 0; kt < kTiles; kt++) {
        int p = kt & 1;
        float4 a4, b4;
        bool more = (kt + 1) < kTiles;
        if (more) {
            a4 = *reinterpret_cast<const float4*>(Aptr + (kt + 1) * 8);
            b4 = *reinterpret_cast<const float4*>(Bptr + (size_t)(kt + 1) * 8 * N);
        }
        #pragma unroll
        for (int k = 0; k < 8; k++) {
            float4 alo = *reinterpret_cast<const float4*>(&As[p][k][ty * 4]);
            float4 ahi = *reinterpret_cast<const float4*>(&As[p][k][ty * 4 + 64]);
            ull aa[8];
            PACK_DUP(aa[0], alo.x); PACK_DUP(aa[1], alo.y);
            PACK_DUP(aa[2], alo.z); PACK_DUP(aa[3], alo.w);
            PACK_DUP(aa[4], ahi.x); PACK_DUP(aa[5], ahi.y);
            PACK_DUP(aa[6], ahi.z); PACK_DUP(aa[7], ahi.w);
            ull bb[4];
            bb[0] = *reinterpret_cast<const ull*>(&Bs[p][k][tx * 4]);
            bb[1] = *reinterpret_cast<const ull*>(&Bs[p][k][tx * 4 + 2]);
            bb[2] = *reinterpret_cast<const ull*>(&Bs[p][k][tx * 4 + 64]);
            bb[3] = *reinterpret_cast<const ull*>(&Bs[p][k][tx * 4 + 66]);
            #pragma unroll
            for (int i = 0; i < 8; i++)
                #pragma unroll
                for (int j = 0; j < 4; j++)
                    FMA_F32X2(acc[i][j], aa[i], bb[j], acc[i][j]);
        }
        if (more) {
            int q = p ^ 1;
            As[q][ac + 0][ar] = a4.x; As[q][ac + 1][ar] = a4.y;
            As[q][ac + 2][ar] = a4.z; As[q][ac + 3][ar] = a4.w;
            *reinterpret_cast<float4*>(&Bs[q][br][bc]) = b4;
        }
        __syncthreads();
    }

    // epilogue
    #pragma unroll
    for (int i = 0; i < 8; i++) {
        int m = bm + ty * 4 + (i < 4 ? i : 60 + i);   // rows ty*4+i and ty*4+64+(i-4)
        #pragma unroll
        for (int half = 0; half < 2; half++) {
            int n = bn + tx * 4 + half * 64;
            unsigned u0, u1, u2, u3;
            UNPACK2(u0, u1, acc[i][half * 2 + 0]);
            UNPACK2(u2, u3, acc[i][half * 2 + 1]);
            float v[4] = {__uint_as_float(u0), __uint_as_float(u1),
                          __uint_as_float(u2), __uint_as_float(u3)};
            float4 res;
            if (residual) res = *reinterpret_cast<const float4*>(&residual[(size_t)m * N + n]);
            float4 bs;
            if (bias) bs = *reinterpret_cast<const float4*>(&bias[n]);
            float out[4];
            #pragma unroll
            for (int j = 0; j < 4; j++) {
                float x = v[j] * alpha;
                if (bias) x += (&bs.x)[j];
                if (act == ACT_RELU)         x = fmaxf(x, 0.0f);
                else if (act == ACT_SIGMOID) x = 1.0f / (1.0f + __expf(-x));
                if (residual) x += (&res.x)[j];
                out[j] = x;
            }
            *reinterpret_cast<float4*>(&C[(size_t)m * N + n]) =
                make_float4(out[0], out[1], out[2], out[3]);
        }
    }
}

// ---------------- attention scores: logits[h,t,r] = q[t,h,:]·k[r,h,:] + BIG*(mask-1) ----------------
__global__ __launch_bounds__(256) void scores_kernel(
    const float* __restrict__ q, const float* __restrict__ k,
    const float* __restrict__ mask, float* __restrict__ logits) {
    int h  = blockIdx.z;
    int bt = blockIdx.y * 64, br = blockIdx.x * 64;
    __shared__ float Qs[KD][64];
    __shared__ float Ks[KD][64];
    int t = threadIdx.x;
    int tx = t & 15, ty = t >> 4;
    #pragma unroll
    for (int i = 0; i < 12; i++) {
        int lin = t + i * 256;               // 0..3071
        int m = lin / KD, c = lin % KD;
        Qs[c][m] = q[(size_t)(bt + m) * C_DIM + h * KD + c];
        Ks[c][m] = k[(size_t)(br + m) * C_DIM + h * KD + c];
    }
    __syncthreads();
    float acc[4][4] = {};
    #pragma unroll 4
    for (int c = 0; c < KD; c++) {
        float4 a4 = *reinterpret_cast<const float4*>(&Qs[c][ty * 4]);
        float4 b4 = *reinterpret_cast<const float4*>(&Ks[c][tx * 4]);
        float a[4] = {a4.x, a4.y, a4.z, a4.w};
        float b[4] = {b4.x, b4.y, b4.z, b4.w};
        #pragma unroll
        for (int i = 0; i < 4; i++)
            #pragma unroll
            for (int j = 0; j < 4; j++)
                acc[i][j] += a[i] * b[j];
    }
    #pragma unroll
    for (int i = 0; i < 4; i++) {
        int tt = bt + ty * 4 + i;
        #pragma unroll
        for (int j = 0; j < 4; j++) {
            int rr = br + tx * 4 + j;
            size_t idx = ((size_t)h * T_TOK + tt) * N_RES + rr;
            logits[idx] = acc[i][j] + BIGF * (mask[idx] - 1.0f);
        }
    }
}

// ---------------- row softmax over R=4096, in place ----------------
__global__ __launch_bounds__(256) void softmax_kernel(float* __restrict__ logits) {
    size_t row = blockIdx.x;
    float* lr = logits + row * N_RES;
    int t = threadIdx.x;
    float e[16];
    float m = -1e30f;
    #pragma unroll
    for (int i = 0; i < 16; i++) { e[i] = lr[t + i * 256]; m = fmaxf(m, e[i]); }
    __shared__ float sh[8];
    __shared__ float red_s;
    int wid = t >> 5, lane = t & 31;
    #pragma unroll
    for (int o = 16; o; o >>= 1) m = fmaxf(m, __shfl_down_sync(0xffffffffu, m, o));
    if (lane == 0) sh[wid] = m;
    __syncthreads();
    if (t == 0) {
        float mm = sh[0];
        #pragma unroll
        for (int w = 1; w < 8; w++) mm = fmaxf(mm, sh[w]);
        red_s = mm;
    }
    __syncthreads();
    m = red_s;
    float s = 0.0f;
    #pragma unroll
    for (int i = 0; i < 16; i++) { e[i] = __expf(e[i] - m); s += e[i]; }
    __syncthreads();
    #pragma unroll
    for (int o = 16; o; o >>= 1) s += __shfl_down_sync(0xffffffffu, s, o);
    if (lane == 0) sh[wid] = s;
    __syncthreads();
    if (t == 0) {
        float ss = 0.0f;
        #pragma unroll
        for (int w = 0; w < 8; w++) ss += sh[w];
        red_s = 1.0f / ss;
    }
    __syncthreads();
    float inv = red_s;
    #pragma unroll
    for (int i = 0; i < 16; i++) lr[t + i * 256] = e[i] * inv;
}

// ---------------- AV: wag[t, h*48+c] = gate * sum_r W[h,t,r] * v[r,h,c] ----------------
__global__ __launch_bounds__(256) void av_kernel(
    const float* __restrict__ w, const float* __restrict__ v,
    const float* __restrict__ gate, float* __restrict__ wag) {
    int h  = blockIdx.y;
    int bt = blockIdx.x * 64;
    __shared__ float Ws[64][65];   // [t][r]
    __shared__ float Vs[64][KD];   // [r][c]
    int t = threadIdx.x;
    int tx = t & 15, ty = t >> 4;  // tx -> 3 c's, ty -> 4 t's
    float acc[4][3] = {};
    for (int r0 = 0; r0 < N_RES; r0 += 64) {
        #pragma unroll
        for (int i = 0; i < 16; i++) {
            int lin = t + i * 256;
            int tt = lin >> 6, rr = lin & 63;
            Ws[tt][rr] = w[((size_t)h * T_TOK + bt + tt) * N_RES + r0 + rr];
        }
        #pragma unroll
        for (int i = 0; i < 12; i++) {
            int lin = t + i * 256;
            int rr = lin / KD, c = lin % KD;
            Vs[rr][c] = v[(size_t)(r0 + rr) * C_DIM + h * KD + c];
        }
        __syncthreads();
        #pragma unroll 4
        for (int rr = 0; rr < 64; rr++) {
            float a[4], b[3];
            #pragma unroll
            for (int i = 0; i < 4; i++) a[i] = Ws[ty * 4 + i][rr];
            #pragma unroll
            for (int j = 0; j < 3; j++) b[j] = Vs[rr][tx * 3 + j];
            #pragma unroll
            for (int i = 0; i < 4; i++)
                #pragma unroll
                for (int j = 0; j < 3; j++)
                    acc[i][j] += a[i] * b[j];
        }
        __syncthreads();
    }
    #pragma unroll
    for (int i = 0; i < 4; i++) {
        int tt = bt + ty * 4 + i;
        #pragma unroll
        for (int j = 0; j < 3; j++) {
            size_t idx = (size_t)tt * C_DIM + h * KD + tx * 3 + j;
            wag[idx] = acc[i][j] * gate[idx];
        }
    }
}

// ---------------- host launch ----------------
static float* sym(const void* s) {
    void* p = nullptr;
    cudaGetSymbolAddress(&p, s);
    return (float*)p;
}

extern "C" void kernel_launch(void* const* d_in, const int* in_sizes, int n_in,
                              void* d_out, int out_size) {
    const float* original   = (const float*)d_in[0];
    const float* resampled  = (const float*)d_in[1];
    const float* attn_mask  = (const float*)d_in[2];
    const float* qn_scale   = (const float*)d_in[5];
    const float* qn_offset  = (const float*)d_in[6];
    const float* dn_scale   = (const float*)d_in[7];
    const float* dn_offset  = (const float*)d_in[8];
    const float* query_w    = (const float*)d_in[9];
    const float* key_w      = (const float*)d_in[10];
    const float* value_w    = (const float*)d_in[11];
    const float* gating_w   = (const float*)d_in[12];
    const float* gating_b   = (const float*)d_in[13];
    const float* output_w   = (const float*)d_in[14];
    const float* output_b   = (const float*)d_in[15];
    const float* rt_ln_scale  = (const float*)d_in[16];
    const float* rt_ln_offset = (const float*)d_in[17];
    const float* rt_w1 = (const float*)d_in[18];
    const float* rt_b1 = (const float*)d_in[19];
    const float* rt_w2 = (const float*)d_in[20];
    const float* rt_b2 = (const float*)d_in[21];
    const float* ot_ln_scale  = (const float*)d_in[22];
    const float* ot_ln_offset = (const float*)d_in[23];
    const float* ot_w1 = (const float*)d_in[24];
    const float* ot_b1 = (const float*)d_in[25];
    const float* ot_w2 = (const float*)d_in[26];
    const float* ot_b2 = (const float*)d_in[27];

    float* out_res  = (float*)d_out;                       // [512, 384]
    float* out_orig = out_res + (size_t)T_TOK * C_DIM;     // [4096, 384]

    float* p_qin  = sym(g_qin);
    float* p_din  = sym(g_din);
    float* p_ln4  = sym(g_ln4);
    float* p_q    = sym(g_q);
    float* p_gate = sym(g_gate);
    float* p_k    = sym(g_k);
    float* p_v    = sym(g_v);
    float* p_log  = sym(g_logits);
    float* p_wag  = sym(g_wag);
    float* p_ln3  = sym(g_ln3);
    float* p_h1   = sym(g_h1);
    float* p_h2   = sym(g_h2);

    const float inv_sqrt_kd = 0.14433756729740643f;  // 1/sqrt(48)

    // LayerNorms on raw inputs
    ln_kernel<<<T_TOK, 128>>>(resampled, qn_scale, qn_offset, p_qin);
    ln_kernel<<<N_RES, 128>>>(original,  dn_scale, dn_offset, p_din);
    ln_kernel<<<N_RES, 128>>>(original,  ot_ln_scale, ot_ln_offset, p_ln4);

    // Projections
    gemm128<<<dim3(C_DIM / 128, T_TOK / 128), 256>>>(p_qin, query_w,  p_q,    T_TOK, C_DIM, C_DIM, inv_sqrt_kd, nullptr,  ACT_NONE,    nullptr);
    gemm128<<<dim3(C_DIM / 128, T_TOK / 128), 256>>>(p_qin, gating_w, p_gate, T_TOK, C_DIM, C_DIM, 1.0f,        gating_b, ACT_SIGMOID, nullptr);
    gemm128<<<dim3(C_DIM / 128, N_RES / 128), 256>>>(p_din, key_w,    p_k,    N_RES, C_DIM, C_DIM, 1.0f,        nullptr,  ACT_NONE,    nullptr);
    gemm128<<<dim3(C_DIM / 128, N_RES / 128), 256>>>(p_din, value_w,  p_v,    N_RES, C_DIM, C_DIM, 1.0f,        nullptr,  ACT_NONE,    nullptr);

    // Attention
    scores_kernel<<<dim3(N_RES / 64, T_TOK / 64, H_HEADS), 256>>>(p_q, p_k, attn_mask, p_log);
    softmax_kernel<<<H_HEADS * T_TOK, 256>>>(p_log);
    av_kernel<<<dim3(T_TOK / 64, H_HEADS), 256>>>(p_log, p_v, p_gate, p_wag);

    // Output projection + residual -> resampled2 (in d_out)
    gemm128<<<dim3(C_DIM / 128, T_TOK / 128), 256>>>(p_wag, output_w, out_res, T_TOK, C_DIM, C_DIM, 1.0f, output_b, ACT_NONE, resampled);

    // resampled transition
    ln_kernel<<<T_TOK, 128>>>(out_res, rt_ln_scale, rt_ln_offset, p_ln3);
    gemm128<<<dim3(F_DIM / 128, T_TOK / 128), 256>>>(p_ln3, rt_w1, p_h1,   T_TOK, F_DIM, C_DIM, 1.0f, rt_b1, ACT_RELU, nullptr);
    gemm128<<<dim3(C_DIM / 128, T_TOK / 128), 256>>>(p_h1,  rt_w2, out_res, T_TOK, C_DIM, F_DIM, 1.0f, rt_b2, ACT_NONE, out_res);

    // original transition
    gemm128<<<dim3(F_DIM / 128, N_RES / 128), 256>>>(p_ln4, ot_w1, p_h2,    N_RES, F_DIM, C_DIM, 1.0f, ot_b1, ACT_RELU, nullptr);
    gemm128<<<dim3(C_DIM / 128, N_RES / 128), 256>>>(p_h2,  ot_w2, out_orig, N_RES, C_DIM, F_DIM, 1.0f, ot_b2, ACT_NONE, original);
}

// round 3
// speedup vs baseline: 1.5170x; 1.3945x over previous
#include <cuda_runtime.h>
#include <math.h>

#define T_TOK 512
#define N_RES 4096
#define C_DIM 384
#define H_HEADS 8
#define KD 48
#define F_DIM 1536
#define LN_EPS 1e-5f
#define BIGF 1e9f

// ---------------- scratch (device globals; no runtime alloc allowed) ----------------
__device__ float g_qin [T_TOK * C_DIM];
__device__ float g_din [N_RES * C_DIM];
__device__ float g_ln4 [N_RES * C_DIM];
__device__ float g_q   [T_TOK * C_DIM];
__device__ float g_gate[T_TOK * C_DIM];
__device__ float g_k   [N_RES * C_DIM];
__device__ float g_v   [N_RES * C_DIM];
__device__ float g_logits[(size_t)H_HEADS * T_TOK * N_RES];   // 67 MB
__device__ float g_wag [T_TOK * C_DIM];
__device__ float g_ln3 [T_TOK * C_DIM];
__device__ float g_h1  [T_TOK * F_DIM];
__device__ float g_h2  [N_RES * F_DIM];

__device__ __forceinline__ float to_tf32(float x) {
    asm("cvt.rna.tf32.f32 %0, %1;" : "=f"(x) : "f"(x));
    return x;
}

#define MMA_TF32(c, a, b) \
    asm volatile("mma.sync.aligned.m16n8k8.row.col.f32.tf32.tf32.f32 " \
        "{%0,%1,%2,%3}, {%4,%5,%6,%7}, {%8,%9}, {%0,%1,%2,%3};" \
        : "+f"((c)[0]), "+f"((c)[1]), "+f"((c)[2]), "+f"((c)[3]) \
        : "r"((a)[0]), "r"((a)[1]), "r"((a)[2]), "r"((a)[3]), \
          "r"((b)[0]), "r"((b)[1]))

// ---------------- LayerNorm: one block (128 thr) per row of 384 ----------------
__global__ void ln_kernel(const float* __restrict__ x, const float* __restrict__ scale,
                          const float* __restrict__ offset, float* __restrict__ out) {
    int row = blockIdx.x;
    const float* xr = x + (size_t)row * C_DIM;
    int t = threadIdx.x;
    float v0 = xr[t], v1 = xr[t + 128], v2 = xr[t + 256];
    float s  = v0 + v1 + v2;
    float s2 = v0 * v0 + v1 * v1 + v2 * v2;
    #pragma unroll
    for (int o = 16; o; o >>= 1) {
        s  += __shfl_down_sync(0xffffffffu, s,  o);
        s2 += __shfl_down_sync(0xffffffffu, s2, o);
    }
    __shared__ float sh[8];
    __shared__ float mu_s, rstd_s;
    int wid = t >> 5, lane = t & 31;
    if (lane == 0) { sh[wid] = s; sh[4 + wid] = s2; }
    __syncthreads();
    if (t == 0) {
        float ts  = sh[0] + sh[1] + sh[2] + sh[3];
        float ts2 = sh[4] + sh[5] + sh[6] + sh[7];
        float mu  = ts * (1.0f / C_DIM);
        float var = ts2 * (1.0f / C_DIM) - mu * mu;
        mu_s = mu; rstd_s = rsqrtf(var + LN_EPS);
    }
    __syncthreads();
    float mu = mu_s, rstd = rstd_s;
    float* orow = out + (size_t)row * C_DIM;
    orow[t]       = scale[t]       * (v0 - mu) * rstd + offset[t];
    orow[t + 128] = scale[t + 128] * (v1 - mu) * rstd + offset[t + 128];
    orow[t + 256] = scale[t + 256] * (v2 - mu) * rstd + offset[t + 256];
}

// ---------------- 128x128x32 tf32 tensor-core GEMM ----------------
// C[M,N] = act(alpha * A@B + bias) + residual   (row-major; M%128==0, N%128==0, K%32==0)
#define ACT_NONE 0
#define ACT_RELU 1
#define ACT_SIGMOID 2

__global__ __launch_bounds__(256) void gemm_tc(
    const float* __restrict__ A, const float* __restrict__ B, float* __restrict__ C,
    int M, int N, int K, float alpha,
    const float* __restrict__ bias, int act, const float* __restrict__ residual) {
    // smem: A tile [128][32] (swizzled cols: c ^ ((m&7)<<2)),
    //       B tile [32][128] (swizzled cols: n ^ ((k&3)<<3))
    __shared__ float As[128 * 32];
    __shared__ float Bs[32 * 128];

    int t = threadIdx.x;
    int bm = blockIdx.y * 128, bn = blockIdx.x * 128;
    int wid = t >> 5, lane = t & 31;
    int wm = (wid >> 2) * 64;       // warp m offset: 0 or 64
    int wn = (wid & 3) * 32;        // warp n offset: 0..96
    int grp = lane >> 2, tig = lane & 3;

    // global load mapping: v = t + i*256
    // A: v over 1024 float4s: m = v>>3, c4 = (v&7)*4
    // B: k = v>>5, n4 = (v&31)*4
    const float* Ap[4];
    const float* Bp[4];
    int   a_m[4], a_c4s[4];         // swizzled store cols
    int   b_k[4], b_n4s[4];
    #pragma unroll
    for (int i = 0; i < 4; i++) {
        int v = t + i * 256;
        int m = v >> 3, c4 = (v & 7) * 4;
        a_m[i] = m; a_c4s[i] = c4 ^ ((m & 7) << 2);
        Ap[i] = A + (size_t)(bm + m) * K + c4;
        int k = v >> 5, n4 = (v & 31) * 4;
        b_k[i] = k; b_n4s[i] = n4 ^ ((k & 3) << 3);
        Bp[i] = B + (size_t)k * N + bn + n4;
    }

    float acc[4][4][4];
    #pragma unroll
    for (int i = 0; i < 4; i++)
        #pragma unroll
        for (int j = 0; j < 4; j++)
            #pragma unroll
            for (int r = 0; r < 4; r++) acc[i][j][r] = 0.0f;

    int kTiles = K >> 5;

    // prologue: tile 0 -> smem (with tf32 convert)
    #pragma unroll
    for (int i = 0; i < 4; i++) {
        float4 a4 = *reinterpret_cast<const float4*>(Ap[i]);
        float4 b4 = *reinterpret_cast<const float4*>(Bp[i]);
        *reinterpret_cast<float4*>(&As[a_m[i] * 32 + a_c4s[i]]) =
            make_float4(to_tf32(a4.x), to_tf32(a4.y), to_tf32(a4.z), to_tf32(a4.w));
        *reinterpret_cast<float4*>(&Bs[b_k[i] * 128 + b_n4s[i]]) =
            make_float4(to_tf32(b4.x), to_tf32(b4.y), to_tf32(b4.z), to_tf32(b4.w));
    }
    __syncthreads();

    for (int kt = 0; kt < kTiles; kt++) {
        bool more = (kt + 1) < kTiles;
        float4 pa[4], pb[4];
        if (more) {
            #pragma unroll
            for (int i = 0; i < 4; i++) {
                pa[i] = *reinterpret_cast<const float4*>(Ap[i] + (kt + 1) * 32);
                pb[i] = *reinterpret_cast<const float4*>(Bp[i] + (size_t)(kt + 1) * 32 * N);
            }
        }
        // compute 4 k8-steps
        #pragma unroll
        for (int s = 0; s < 4; s++) {
            int k8 = s * 8;
            int kc_lo = (k8 + tig) ^ (grp << 2);
            int kc_hi = (k8 + 4 + tig) ^ (grp << 2);
            unsigned af[4][4];
            #pragma unroll
            for (int fm = 0; fm < 4; fm++) {
                int r0 = wm + fm * 16 + grp;
                af[fm][0] = __float_as_uint(As[r0 * 32 + kc_lo]);
                af[fm][1] = __float_as_uint(As[(r0 + 8) * 32 + kc_lo]);
                af[fm][2] = __float_as_uint(As[r0 * 32 + kc_hi]);
                af[fm][3] = __float_as_uint(As[(r0 + 8) * 32 + kc_hi]);
            }
            unsigned bf[4][2];
            #pragma unroll
            for (int fn = 0; fn < 4; fn++) {
                int ncol = (wn + fn * 8 + grp) ^ (tig << 3);
                bf[fn][0] = __float_as_uint(Bs[(k8 + tig) * 128 + ncol]);
                bf[fn][1] = __float_as_uint(Bs[(k8 + 4 + tig) * 128 + ncol]);
            }
            #pragma unroll
            for (int fm = 0; fm < 4; fm++)
                #pragma unroll
                for (int fn = 0; fn < 4; fn++)
                    MMA_TF32(acc[fm][fn], af[fm], bf[fn]);
        }
        __syncthreads();
        if (more) {
            #pragma unroll
            for (int i = 0; i < 4; i++) {
                *reinterpret_cast<float4*>(&As[a_m[i] * 32 + a_c4s[i]]) =
                    make_float4(to_tf32(pa[i].x), to_tf32(pa[i].y), to_tf32(pa[i].z), to_tf32(pa[i].w));
                *reinterpret_cast<float4*>(&Bs[b_k[i] * 128 + b_n4s[i]]) =
                    make_float4(to_tf32(pb[i].x), to_tf32(pb[i].y), to_tf32(pb[i].z), to_tf32(pb[i].w));
            }
            __syncthreads();
        }
    }

    // epilogue
    #pragma unroll
    for (int fm = 0; fm < 4; fm++) {
        #pragma unroll
        for (int fn = 0; fn < 4; fn++) {
            int m0 = bm + wm + fm * 16 + grp;
            int n  = bn + wn + fn * 8 + tig * 2;
            #pragma unroll
            for (int half = 0; half < 2; half++) {
                int m = m0 + half * 8;
                float x0 = acc[fm][fn][half * 2 + 0] * alpha;
                float x1 = acc[fm][fn][half * 2 + 1] * alpha;
                if (bias) { x0 += bias[n]; x1 += bias[n + 1]; }
                if (act == ACT_RELU) {
                    x0 = fmaxf(x0, 0.0f); x1 = fmaxf(x1, 0.0f);
                } else if (act == ACT_SIGMOID) {
                    x0 = 1.0f / (1.0f + __expf(-x0));
                    x1 = 1.0f / (1.0f + __expf(-x1));
                }
                if (residual) {
                    float2 r = *reinterpret_cast<const float2*>(&residual[(size_t)m * N + n]);
                    x0 += r.x; x1 += r.y;
                }
                *reinterpret_cast<float2*>(&C[(size_t)m * N + n]) = make_float2(x0, x1);
            }
        }
    }
}

// ---------------- attention scores: logits[h,t,r] = q[t,h,:]·k[r,h,:] + BIG*(mask-1) ----------------
__global__ __launch_bounds__(256) void scores_kernel(
    const float* __restrict__ q, const float* __restrict__ k,
    const float* __restrict__ mask, float* __restrict__ logits) {
    int h  = blockIdx.z;
    int bt = blockIdx.y * 64, br = blockIdx.x * 64;
    __shared__ float Qs[KD][64];
    __shared__ float Ks[KD][64];
    int t = threadIdx.x;
    int tx = t & 15, ty = t >> 4;
    #pragma unroll
    for (int i = 0; i < 12; i++) {
        int lin = t + i * 256;               // 0..3071
        int m = lin / KD, c = lin % KD;
        Qs[c][m] = q[(size_t)(bt + m) * C_DIM + h * KD + c];
        Ks[c][m] = k[(size_t)(br + m) * C_DIM + h * KD + c];
    }
    __syncthreads();
    float acc[4][4] = {};
    #pragma unroll 4
    for (int c = 0; c < KD; c++) {
        float4 a4 = *reinterpret_cast<const float4*>(&Qs[c][ty * 4]);
        float4 b4 = *reinterpret_cast<const float4*>(&Ks[c][tx * 4]);
        float a[4] = {a4.x, a4.y, a4.z, a4.w};
        float b[4] = {b4.x, b4.y, b4.z, b4.w};
        #pragma unroll
        for (int i = 0; i < 4; i++)
            #pragma unroll
            for (int j = 0; j < 4; j++)
                acc[i][j] += a[i] * b[j];
    }
    #pragma unroll
    for (int i = 0; i < 4; i++) {
        int tt = bt + ty * 4 + i;
        #pragma unroll
        for (int j = 0; j < 4; j++) {
            int rr = br + tx * 4 + j;
            size_t idx = ((size_t)h * T_TOK + tt) * N_RES + rr;
            logits[idx] = acc[i][j] + BIGF * (mask[idx] - 1.0f);
        }
    }
}

// ---------------- row softmax over R=4096, in place ----------------
__global__ __launch_bounds__(256) void softmax_kernel(float* __restrict__ logits) {
    size_t row = blockIdx.x;
    float* lr = logits + row * N_RES;
    int t = threadIdx.x;
    float e[16];
    float m = -1e30f;
    #pragma unroll
    for (int i = 0; i < 16; i++) { e[i] = lr[t + i * 256]; m = fmaxf(m, e[i]); }
    __shared__ float sh[8];
    __shared__ float red_s;
    int wid = t >> 5, lane = t & 31;
    #pragma unroll
    for (int o = 16; o; o >>= 1) m = fmaxf(m, __shfl_down_sync(0xffffffffu, m, o));
    if (lane == 0) sh[wid] = m;
    __syncthreads();
    if (t == 0) {
        float mm = sh[0];
        #pragma unroll
        for (int w = 1; w < 8; w++) mm = fmaxf(mm, sh[w]);
        red_s = mm;
    }
    __syncthreads();
    m = red_s;
    float s = 0.0f;
    #pragma unroll
    for (int i = 0; i < 16; i++) { e[i] = __expf(e[i] - m); s += e[i]; }
    __syncthreads();
    #pragma unroll
    for (int o = 16; o; o >>= 1) s += __shfl_down_sync(0xffffffffu, s, o);
    if (lane == 0) sh[wid] = s;
    __syncthreads();
    if (t == 0) {
        float ss = 0.0f;
        #pragma unroll
        for (int w = 0; w < 8; w++) ss += sh[w];
        red_s = 1.0f / ss;
    }
    __syncthreads();
    float inv = red_s;
    #pragma unroll
    for (int i = 0; i < 16; i++) lr[t + i * 256] = e[i] * inv;
}

// ---------------- AV: wag[t, h*48+c] = gate * sum_r W[h,t,r] * v[r,h,c] ----------------
__global__ __launch_bounds__(256) void av_kernel(
    const float* __restrict__ w, const float* __restrict__ v,
    const float* __restrict__ gate, float* __restrict__ wag) {
    int h  = blockIdx.y;
    int bt = blockIdx.x * 64;
    __shared__ float Ws[64][65];   // [t][r]
    __shared__ float Vs[64][KD];   // [r][c]
    int t = threadIdx.x;
    int tx = t & 15, ty = t >> 4;  // tx -> 3 c's, ty -> 4 t's
    float acc[4][3] = {};
    for (int r0 = 0; r0 < N_RES; r0 += 64) {
        #pragma unroll
        for (int i = 0; i < 16; i++) {
            int lin = t + i * 256;
            int tt = lin >> 6, rr = lin & 63;
            Ws[tt][rr] = w[((size_t)h * T_TOK + bt + tt) * N_RES + r0 + rr];
        }
        #pragma unroll
        for (int i = 0; i < 12; i++) {
            int lin = t + i * 256;
            int rr = lin / KD, c = lin % KD;
            Vs[rr][c] = v[(size_t)(r0 + rr) * C_DIM + h * KD + c];
        }
        __syncthreads();
        #pragma unroll 4
        for (int rr = 0; rr < 64; rr++) {
            float a[4], b[3];
            #pragma unroll
            for (int i = 0; i < 4; i++) a[i] = Ws[ty * 4 + i][rr];
            #pragma unroll
            for (int j = 0; j < 3; j++) b[j] = Vs[rr][tx * 3 + j];
            #pragma unroll
            for (int i = 0; i < 4; i++)
                #pragma unroll
                for (int j = 0; j < 3; j++)
                    acc[i][j] += a[i] * b[j];
        }
        __syncthreads();
    }
    #pragma unroll
    for (int i = 0; i < 4; i++) {
        int tt = bt + ty * 4 + i;
        #pragma unroll
        for (int j = 0; j < 3; j++) {
            size_t idx = (size_t)tt * C_DIM + h * KD + tx * 3 + j;
            wag[idx] = acc[i][j] * gate[idx];
        }
    }
}

// ---------------- host launch ----------------
static float* sym(const void* s) {
    void* p = nullptr;
    cudaGetSymbolAddress(&p, s);
    return (float*)p;
}

extern "C" void kernel_launch(void* const* d_in, const int* in_sizes, int n_in,
                              void* d_out, int out_size) {
    const float* original   = (const float*)d_in[0];
    const float* resampled  = (const float*)d_in[1];
    const float* attn_mask  = (const float*)d_in[2];
    const float* qn_scale   = (const float*)d_in[5];
    const float* qn_offset  = (const float*)d_in[6];
    const float* dn_scale   = (const float*)d_in[7];
    const float* dn_offset  = (const float*)d_in[8];
    const float* query_w    = (const float*)d_in[9];
    const float* key_w      = (const float*)d_in[10];
    const float* value_w    = (const float*)d_in[11];
    const float* gating_w   = (const float*)d_in[12];
    const float* gating_b   = (const float*)d_in[13];
    const float* output_w   = (const float*)d_in[14];
    const float* output_b   = (const float*)d_in[15];
    const float* rt_ln_scale  = (const float*)d_in[16];
    const float* rt_ln_offset = (const float*)d_in[17];
    const float* rt_w1 = (const float*)d_in[18];
    const float* rt_b1 = (const float*)d_in[19];
    const float* rt_w2 = (const float*)d_in[20];
    const float* rt_b2 = (const float*)d_in[21];
    const float* ot_ln_scale  = (const float*)d_in[22];
    const float* ot_ln_offset = (const float*)d_in[23];
    const float* ot_w1 = (const float*)d_in[24];
    const float* ot_b1 = (const float*)d_in[25];
    const float* ot_w2 = (const float*)d_in[26];
    const float* ot_b2 = (const float*)d_in[27];

    float* out_res  = (float*)d_out;                       // [512, 384]
    float* out_orig = out_res + (size_t)T_TOK * C_DIM;     // [4096, 384]

    float* p_qin  = sym(g_qin);
    float* p_din  = sym(g_din);
    float* p_ln4  = sym(g_ln4);
    float* p_q    = sym(g_q);
    float* p_gate = sym(g_gate);
    float* p_k    = sym(g_k);
    float* p_v    = sym(g_v);
    float* p_log  = sym(g_logits);
    float* p_wag  = sym(g_wag);
    float* p_ln3  = sym(g_ln3);
    float* p_h1   = sym(g_h1);
    float* p_h2   = sym(g_h2);

    const float inv_sqrt_kd = 0.14433756729740643f;  // 1/sqrt(48)

    // LayerNorms on raw inputs
    ln_kernel<<<T_TOK, 128>>>(resampled, qn_scale, qn_offset, p_qin);
    ln_kernel<<<N_RES, 128>>>(original,  dn_scale, dn_offset, p_din);
    ln_kernel<<<N_RES, 128>>>(original,  ot_ln_scale, ot_ln_offset, p_ln4);

    // Projections (tf32 tensor cores)
    gemm_tc<<<dim3(C_DIM / 128, T_TOK / 128), 256>>>(p_qin, query_w,  p_q,    T_TOK, C_DIM, C_DIM, inv_sqrt_kd, nullptr,  ACT_NONE,    nullptr);
    gemm_tc<<<dim3(C_DIM / 128, T_TOK / 128), 256>>>(p_qin, gating_w, p_gate, T_TOK, C_DIM, C_DIM, 1.0f,        gating_b, ACT_SIGMOID, nullptr);
    gemm_tc<<<dim3(C_DIM / 128, N_RES / 128), 256>>>(p_din, key_w,    p_k,    N_RES, C_DIM, C_DIM, 1.0f,        nullptr,  ACT_NONE,    nullptr);
    gemm_tc<<<dim3(C_DIM / 128, N_RES / 128), 256>>>(p_din, value_w,  p_v,    N_RES, C_DIM, C_DIM, 1.0f,        nullptr,  ACT_NONE,    nullptr);

    // Attention
    scores_kernel<<<dim3(N_RES / 64, T_TOK / 64, H_HEADS), 256>>>(p_q, p_k, attn_mask, p_log);
    softmax_kernel<<<H_HEADS * T_TOK, 256>>>(p_log);
    av_kernel<<<dim3(T_TOK / 64, H_HEADS), 256>>>(p_log, p_v, p_gate, p_wag);

    // Output projection + residual -> resampled2 (in d_out)
    gemm_tc<<<dim3(C_DIM / 128, T_TOK / 128), 256>>>(p_wag, output_w, out_res, T_TOK, C_DIM, C_DIM, 1.0f, output_b, ACT_NONE, resampled);

    // resampled transition
    ln_kernel<<<T_TOK, 128>>>(out_res, rt_ln_scale, rt_ln_offset, p_ln3);
    gemm_tc<<<dim3(F_DIM / 128, T_TOK / 128), 256>>>(p_ln3, rt_w1, p_h1,   T_TOK, F_DIM, C_DIM, 1.0f, rt_b1, ACT_RELU, nullptr);
    gemm_tc<<<dim3(C_DIM / 128, T_TOK / 128), 256>>>(p_h1,  rt_w2, out_res, T_TOK, C_DIM, F_DIM, 1.0f, rt_b2, ACT_NONE, out_res);

    // original transition
    gemm_tc<<<dim3(F_DIM / 128, N_RES / 128), 256>>>(p_ln4, ot_w1, p_h2,    N_RES, F_DIM, C_DIM, 1.0f, ot_b1, ACT_RELU, nullptr);
    gemm_tc<<<dim3(C_DIM / 128, N_RES / 128), 256>>>(p_h2,  ot_w2, out_orig, N_RES, C_DIM, F_DIM, 1.0f, ot_b2, ACT_NONE, original);
}

// round 4
// speedup vs baseline: 3.5363x; 2.3311x over previous
#include <cuda_runtime.h>
#include <math.h>

#define T_TOK 512
#define N_RES 4096
#define C_DIM 384
#define H_HEADS 8
#define KD 48
#define F_DIM 1536
#define LN_EPS 1e-5f
#define BIGF 1e9f
#define RSPLIT 2
#define RCHUNK 64
#define STAGES 3

// ---------------- scratch (device globals; no runtime alloc allowed) ----------------
__device__ float g_qin [T_TOK * C_DIM];
__device__ float g_din [N_RES * C_DIM];
__device__ float g_ln4 [N_RES * C_DIM];
__device__ float g_q   [T_TOK * C_DIM];
__device__ float g_gate[T_TOK * C_DIM];
__device__ float g_k   [N_RES * C_DIM];
__device__ float g_v   [N_RES * C_DIM];
__device__ float g_wag [T_TOK * C_DIM];
__device__ float g_ln3 [T_TOK * C_DIM];
__device__ float g_h1  [T_TOK * F_DIM];
__device__ float g_h2  [N_RES * F_DIM];
// tf32-rounded weights (concatenated)
#define OFF_QW  0
#define OFF_KW  147456
#define OFF_VW  294912
#define OFF_GW  442368
#define OFF_OW  589824
#define OFF_RT1 737280
#define OFF_RT2 1327104
#define OFF_OT1 1916928
#define OFF_OT2 2506752
#define WTS_TOTAL 3096576
__device__ float g_wts[WTS_TOTAL];
// flash partials
__device__ float g_po[RSPLIT * H_HEADS * T_TOK * KD];
__device__ float g_pm[RSPLIT * H_HEADS * T_TOK];
__device__ float g_pl[RSPLIT * H_HEADS * T_TOK];

__device__ __forceinline__ float to_tf32(float x) {
    asm("cvt.rna.tf32.f32 %0, %1;" : "=f"(x) : "f"(x));
    return x;
}

#define MMA_TF32(c, a, b) \
    asm volatile("mma.sync.aligned.m16n8k8.row.col.f32.tf32.tf32.f32 " \
        "{%0,%1,%2,%3}, {%4,%5,%6,%7}, {%8,%9}, {%0,%1,%2,%3};" \
        : "+f"((c)[0]), "+f"((c)[1]), "+f"((c)[2]), "+f"((c)[3]) \
        : "r"((a)[0]), "r"((a)[1]), "r"((a)[2]), "r"((a)[3]), \
          "r"((b)[0]), "r"((b)[1]))

__device__ __forceinline__ void cp16(float* dst, const float* src) {
    unsigned d = (unsigned)__cvta_generic_to_shared(dst);
    asm volatile("cp.async.ca.shared.global [%0], [%1], 16;" :: "r"(d), "l"(src));
}
#define CP_COMMIT() asm volatile("cp.async.commit_group;")
#define CP_WAIT(n)  asm volatile("cp.async.wait_group %0;" :: "n"(n))

// ---------------- weight rounding: float4 cvt.rna copy ----------------
__global__ void round4_kernel(const float* __restrict__ src, float* __restrict__ dst, int n4) {
    int i = blockIdx.x * blockDim.x + threadIdx.x;
    if (i < n4) {
        float4 v = reinterpret_cast<const float4*>(src)[i];
        reinterpret_cast<float4*>(dst)[i] =
            make_float4(to_tf32(v.x), to_tf32(v.y), to_tf32(v.z), to_tf32(v.w));
    }
}

// ---------------- LayerNorm: one block (128 thr) per row of 384, tf32-rounded out ----------------
__global__ void ln_kernel(const float* __restrict__ x, const float* __restrict__ scale,
                          const float* __restrict__ offset, float* __restrict__ out) {
    int row = blockIdx.x;
    const float* xr = x + (size_t)row * C_DIM;
    int t = threadIdx.x;
    float v0 = xr[t], v1 = xr[t + 128], v2 = xr[t + 256];
    float s  = v0 + v1 + v2;
    float s2 = v0 * v0 + v1 * v1 + v2 * v2;
    #pragma unroll
    for (int o = 16; o; o >>= 1) {
        s  += __shfl_down_sync(0xffffffffu, s,  o);
        s2 += __shfl_down_sync(0xffffffffu, s2, o);
    }
    __shared__ float sh[8];
    __shared__ float mu_s, rstd_s;
    int wid = t >> 5, lane = t & 31;
    if (lane == 0) { sh[wid] = s; sh[4 + wid] = s2; }
    __syncthreads();
    if (t == 0) {
        float ts  = sh[0] + sh[1] + sh[2] + sh[3];
        float ts2 = sh[4] + sh[5] + sh[6] + sh[7];
        float mu  = ts * (1.0f / C_DIM);
        float var = ts2 * (1.0f / C_DIM) - mu * mu;
        mu_s = mu; rstd_s = rsqrtf(var + LN_EPS);
    }
    __syncthreads();
    float mu = mu_s, rstd = rstd_s;
    float* orow = out + (size_t)row * C_DIM;
    orow[t]       = to_tf32(scale[t]       * (v0 - mu) * rstd + offset[t]);
    orow[t + 128] = to_tf32(scale[t + 128] * (v1 - mu) * rstd + offset[t + 128]);
    orow[t + 256] = to_tf32(scale[t + 256] * (v2 - mu) * rstd + offset[t + 256]);
}

// ---------------- 128x128x32, 3-stage cp.async pipelined tf32 GEMM ----------------
// Inputs A,B must already be tf32-rounded. round_out: cvt.rna stored values.
#define ACT_NONE 0
#define ACT_RELU 1
#define ACT_SIGMOID 2

__global__ __launch_bounds__(256, 2) void gemm_tc(
    const float* __restrict__ A, const float* __restrict__ B, float* __restrict__ C,
    int M, int N, int K, float alpha,
    const float* __restrict__ bias, int act, const float* __restrict__ residual,
    int round_out) {
    extern __shared__ float smg[];
    float* As = smg;                      // STAGES * 128*32, swizzled
    float* Bs = smg + STAGES * 4096;      // STAGES * 32*128, swizzled

    int t = threadIdx.x;
    int bm = blockIdx.y * 128, bn = blockIdx.x * 128;
    int wid = t >> 5, lane = t & 31, grp = lane >> 2, tig = lane & 3;
    int wm = (wid >> 2) * 64;   // 0 or 64
    int wn = (wid & 3) * 32;    // 0..96

    // per-thread load mapping (4 float4 each for A and B)
    int a_dst[4], b_dst[4];
    size_t a_src[4], b_src[4];
    #pragma unroll
    for (int i = 0; i < 4; i++) {
        int idx = t + i * 256;
        int am = idx >> 3, af = idx & 7;
        a_dst[i] = (am * 8 + (af ^ (am & 7))) * 4;
        a_src[i] = (size_t)(bm + am) * K + af * 4;
        int bk = idx >> 5, bf = idx & 31;
        b_dst[i] = (bk * 32 + (bf ^ ((bk & 3) << 1))) * 4;
        b_src[i] = (size_t)bk * N + bn + bf * 4;
    }

    float acc[4][4][4];
    #pragma unroll
    for (int i = 0; i < 4; i++)
        #pragma unroll
        for (int j = 0; j < 4; j++)
            #pragma unroll
            for (int r = 0; r < 4; r++) acc[i][j][r] = 0.0f;

    int kTiles = K >> 5;

    // prologue: issue tiles 0 and 1
    #pragma unroll
    for (int pt = 0; pt < STAGES - 1; pt++) {
        float* ab = As + pt * 4096;
        float* bb = Bs + pt * 4096;
        #pragma unroll
        for (int i = 0; i < 4; i++) {
            cp16(ab + a_dst[i], A + a_src[i] + pt * 32);
            cp16(bb + b_dst[i], B + b_src[i] + (size_t)pt * 32 * N);
        }
        CP_COMMIT();
    }

    for (int kt = 0; kt < kTiles; kt++) {
        CP_WAIT(STAGES - 2);
        __syncthreads();
        // issue tile kt+STAGES-1 into buf (kt-1)%STAGES (free since last iter's sync)
        int nt = kt + STAGES - 1;
        if (nt < kTiles) {
            int buf = nt % STAGES;
            float* ab = As + buf * 4096;
            float* bb = Bs + buf * 4096;
            #pragma unroll
            for (int i = 0; i < 4; i++) {
                cp16(ab + a_dst[i], A + a_src[i] + nt * 32);
                cp16(bb + b_dst[i], B + b_src[i] + (size_t)nt * 32 * N);
            }
        }
        CP_COMMIT();
        // compute on buf kt%STAGES
        const float* as = As + (kt % STAGES) * 4096;
        const float* bs = Bs + (kt % STAGES) * 4096;
        #pragma unroll
        for (int s = 0; s < 4; s++) {
            int k0 = s * 8;
            unsigned af[4][4];
            #pragma unroll
            for (int fm = 0; fm < 4; fm++) {
                int m = wm + fm * 16 + grp;
                int swl = 4 * ((2 * s) ^ grp);
                int swh = 4 * ((2 * s + 1) ^ grp);
                af[fm][0] = __float_as_uint(as[m * 32 + tig + swl]);
                af[fm][1] = __float_as_uint(as[(m + 8) * 32 + tig + swl]);
                af[fm][2] = __float_as_uint(as[m * 32 + tig + swh]);
                af[fm][3] = __float_as_uint(as[(m + 8) * 32 + tig + swh]);
            }
            unsigned bf[4][2];
            #pragma unroll
            for (int fn = 0; fn < 4; fn++) {
                int n = wn + fn * 8 + grp;
                int col = (n & 3) + 4 * ((n >> 2) ^ (2 * tig));
                bf[fn][0] = __float_as_uint(bs[(k0 + tig) * 128 + col]);
                bf[fn][1] = __float_as_uint(bs[(k0 + 4 + tig) * 128 + col]);
            }
            #pragma unroll
            for (int fm = 0; fm < 4; fm++)
                #pragma unroll
                for (int fn = 0; fn < 4; fn++)
                    MMA_TF32(acc[fm][fn], af[fm], bf[fn]);
        }
        __syncthreads();
    }

    // epilogue
    #pragma unroll
    for (int fm = 0; fm < 4; fm++) {
        #pragma unroll
        for (int fn = 0; fn < 4; fn++) {
            int m0 = bm + wm + fm * 16 + grp;
            int n  = bn + wn + fn * 8 + tig * 2;
            #pragma unroll
            for (int half = 0; half < 2; half++) {
                int m = m0 + half * 8;
                float x0 = acc[fm][fn][half * 2 + 0] * alpha;
                float x1 = acc[fm][fn][half * 2 + 1] * alpha;
                if (bias) { x0 += bias[n]; x1 += bias[n + 1]; }
                if (act == ACT_RELU) {
                    x0 = fmaxf(x0, 0.0f); x1 = fmaxf(x1, 0.0f);
                } else if (act == ACT_SIGMOID) {
                    x0 = 1.0f / (1.0f + __expf(-x0));
                    x1 = 1.0f / (1.0f + __expf(-x1));
                }
                if (residual) {
                    float2 r = *reinterpret_cast<const float2*>(&residual[(size_t)m * N + n]);
                    x0 += r.x; x1 += r.y;
                }
                if (round_out) { x0 = to_tf32(x0); x1 = to_tf32(x1); }
                *reinterpret_cast<float2*>(&C[(size_t)m * N + n]) = make_float2(x0, x1);
            }
        }
    }
}

// ---------------- flash attention: per block (64 t-rows, head, r-split) ----------------
// smem (floats): Qs[64*52] | Ks[2][64*52] | Vs[2][64*56] | Ms[2][64*68] (mask->P reuse)
#define QS_PITCH 52
#define VS_PITCH 56
#define MS_PITCH 68
#define FL_QS 0
#define FL_KS (64*52)
#define FL_VS (FL_KS + 2*64*52)
#define FL_MS (FL_VS + 2*64*56)
#define FL_TOTAL (FL_MS + 2*64*68)

__global__ __launch_bounds__(128) void flash_kernel(
    const float* __restrict__ q, const float* __restrict__ k,
    const float* __restrict__ v, const float* __restrict__ mask,
    float* __restrict__ po, float* __restrict__ pm, float* __restrict__ pl) {
    extern __shared__ float sm[];
    float* Qs = sm + FL_QS;
    int t = threadIdx.x;
    int wid = t >> 5, lane = t & 31, grp = lane >> 2, tig = lane & 3;
    int t0 = blockIdx.x * 64;
    int h  = blockIdx.y;
    int rsp = blockIdx.z;
    int rbase = rsp * (N_RES / RSPLIT);
    int wr = wid * 16;

    // load Q (pre-scaled, pre-rounded)
    for (int i = t; i < 64 * 12; i += 128) {
        int r = i / 12, f = i % 12;
        float4 q4 = *reinterpret_cast<const float4*>(&q[(size_t)(t0 + r) * C_DIM + h * KD + f * 4]);
        *reinterpret_cast<float4*>(&Qs[r * QS_PITCH + f * 4]) = q4;
    }

    const int NCH = (N_RES / RSPLIT) / RCHUNK;   // 32

    // issue chunk loads into buffer b
    auto issue = [&](int ch, int b) {
        int r0 = rbase + ch * RCHUNK;
        float* ks = sm + FL_KS + b * 64 * QS_PITCH;
        float* vs = sm + FL_VS + b * 64 * VS_PITCH;
        float* ms = sm + FL_MS + b * 64 * MS_PITCH;
        for (int i = t; i < 64 * 12; i += 128) {
            int r = i / 12, f = i % 12;
            size_t src = (size_t)(r0 + r) * C_DIM + h * KD + f * 4;
            cp16(&ks[r * QS_PITCH + f * 4], &k[src]);
            cp16(&vs[r * VS_PITCH + f * 4], &v[src]);
        }
        for (int i = t; i < 64 * 16; i += 128) {
            int rr = i / 16, f = i % 16;
            cp16(&ms[rr * MS_PITCH + f * 4],
                 &mask[((size_t)h * T_TOK + t0 + rr) * N_RES + r0 + f * 4]);
        }
    };

    issue(0, 0); CP_COMMIT();
    issue(1, 1); CP_COMMIT();

    float m_lo = -1e30f, m_hi = -1e30f, l_lo = 0.0f, l_hi = 0.0f;
    float acc_o[6][4];
    #pragma unroll
    for (int i = 0; i < 6; i++)
        #pragma unroll
        for (int e = 0; e < 4; e++) acc_o[i][e] = 0.0f;

    for (int ch = 0; ch < NCH; ch++) {
        int b = ch & 1;
        CP_WAIT(1);
        __syncthreads();
        float* ks = sm + FL_KS + b * 64 * QS_PITCH;
        float* vs = sm + FL_VS + b * 64 * VS_PITCH;
        float* ms = sm + FL_MS + b * 64 * MS_PITCH;

        // S = Q @ K^T  (per warp: 16 rows x 64 cols)
        float acc_s[8][4];
        #pragma unroll
        for (int fn = 0; fn < 8; fn++)
            #pragma unroll
            for (int e = 0; e < 4; e++) acc_s[fn][e] = 0.0f;
        #pragma unroll
        for (int s = 0; s < 6; s++) {
            int k0 = s * 8;
            unsigned a[4];
            a[0] = __float_as_uint(Qs[(wr + grp) * QS_PITCH + k0 + tig]);
            a[1] = __float_as_uint(Qs[(wr + grp + 8) * QS_PITCH + k0 + tig]);
            a[2] = __float_as_uint(Qs[(wr + grp) * QS_PITCH + k0 + 4 + tig]);
            a[3] = __float_as_uint(Qs[(wr + grp + 8) * QS_PITCH + k0 + 4 + tig]);
            #pragma unroll
            for (int fn = 0; fn < 8; fn++) {
                unsigned bb[2];
                bb[0] = __float_as_uint(ks[(fn * 8 + grp) * QS_PITCH + k0 + tig]);
                bb[1] = __float_as_uint(ks[(fn * 8 + grp) * QS_PITCH + k0 + 4 + tig]);
                MMA_TF32(acc_s[fn], a, bb);
            }
        }
        // bias + row max
        float mx_lo = -1e30f, mx_hi = -1e30f;
        #pragma unroll
        for (int fn = 0; fn < 8; fn++) {
            int col = fn * 8 + 2 * tig;
            float2 blo = *reinterpret_cast<float2*>(&ms[(wr + grp) * MS_PITCH + col]);
            float2 bhi = *reinterpret_cast<float2*>(&ms[(wr + grp + 8) * MS_PITCH + col]);
            acc_s[fn][0] += BIGF * (blo.x - 1.0f);
            acc_s[fn][1] += BIGF * (blo.y - 1.0f);
            acc_s[fn][2] += BIGF * (bhi.x - 1.0f);
            acc_s[fn][3] += BIGF * (bhi.y - 1.0f);
            mx_lo = fmaxf(mx_lo, fmaxf(acc_s[fn][0], acc_s[fn][1]));
            mx_hi = fmaxf(mx_hi, fmaxf(acc_s[fn][2], acc_s[fn][3]));
        }
        mx_lo = fmaxf(mx_lo, __shfl_xor_sync(0xffffffffu, mx_lo, 1));
        mx_lo = fmaxf(mx_lo, __shfl_xor_sync(0xffffffffu, mx_lo, 2));
        mx_hi = fmaxf(mx_hi, __shfl_xor_sync(0xffffffffu, mx_hi, 1));
        mx_hi = fmaxf(mx_hi, __shfl_xor_sync(0xffffffffu, mx_hi, 2));
        float mn_lo = fmaxf(m_lo, mx_lo), mn_hi = fmaxf(m_hi, mx_hi);
        float sc_lo = __expf(m_lo - mn_lo), sc_hi = __expf(m_hi - mn_hi);
        m_lo = mn_lo; m_hi = mn_hi;
        // P = exp(S - m), write to smem (reuse mask buffer; lane-private addresses)
        float rs_lo = 0.0f, rs_hi = 0.0f;
        #pragma unroll
        for (int fn = 0; fn < 8; fn++) {
            int col = fn * 8 + 2 * tig;
            float p0 = __expf(acc_s[fn][0] - mn_lo);
            float p1 = __expf(acc_s[fn][1] - mn_lo);
            float p2 = __expf(acc_s[fn][2] - mn_hi);
            float p3 = __expf(acc_s[fn][3] - mn_hi);
            rs_lo += p0 + p1; rs_hi += p2 + p3;
            *reinterpret_cast<float2*>(&ms[(wr + grp) * MS_PITCH + col]) =
                make_float2(to_tf32(p0), to_tf32(p1));
            *reinterpret_cast<float2*>(&ms[(wr + grp + 8) * MS_PITCH + col]) =
                make_float2(to_tf32(p2), to_tf32(p3));
        }
        rs_lo += __shfl_xor_sync(0xffffffffu, rs_lo, 1);
        rs_lo += __shfl_xor_sync(0xffffffffu, rs_lo, 2);
        rs_hi += __shfl_xor_sync(0xffffffffu, rs_hi, 1);
        rs_hi += __shfl_xor_sync(0xffffffffu, rs_hi, 2);
        l_lo = l_lo * sc_lo + rs_lo;
        l_hi = l_hi * sc_hi + rs_hi;
        #pragma unroll
        for (int fn = 0; fn < 6; fn++) {
            acc_o[fn][0] *= sc_lo; acc_o[fn][1] *= sc_lo;
            acc_o[fn][2] *= sc_hi; acc_o[fn][3] *= sc_hi;
        }
        __syncwarp();
        // O += P @ V
        #pragma unroll
        for (int s = 0; s < 8; s++) {
            int k0 = s * 8;
            unsigned a[4];
            a[0] = __float_as_uint(ms[(wr + grp) * MS_PITCH + k0 + tig]);
            a[1] = __float_as_uint(ms[(wr + grp + 8) * MS_PITCH + k0 + tig]);
            a[2] = __float_as_uint(ms[(wr + grp) * MS_PITCH + k0 + 4 + tig]);
            a[3] = __float_as_uint(ms[(wr + grp + 8) * MS_PITCH + k0 + 4 + tig]);
            #pragma unroll
            for (int fn = 0; fn < 6; fn++) {
                unsigned bb[2];
                bb[0] = __float_as_uint(vs[(k0 + tig) * VS_PITCH + fn * 8 + grp]);
                bb[1] = __float_as_uint(vs[(k0 + 4 + tig) * VS_PITCH + fn * 8 + grp]);
                MMA_TF32(acc_o[fn], a, bb);
            }
        }
        __syncthreads();
        if (ch + 2 < NCH) issue(ch + 2, b);
        CP_COMMIT();
    }

    // write partials
    int row_lo = (rsp * H_HEADS + h) * T_TOK + t0 + wr + grp;
    int row_hi = row_lo + 8;
    #pragma unroll
    for (int fn = 0; fn < 6; fn++) {
        int c = fn * 8 + 2 * tig;
        *reinterpret_cast<float2*>(&po[(size_t)row_lo * KD + c]) =
            make_float2(acc_o[fn][0], acc_o[fn][1]);
        *reinterpret_cast<float2*>(&po[(size_t)row_hi * KD + c]) =
            make_float2(acc_o[fn][2], acc_o[fn][3]);
    }
    if (tig == 0) {
        pm[row_lo] = m_lo; pm[row_hi] = m_hi;
        pl[row_lo] = l_lo; pl[row_hi] = l_hi;
    }
}

// ---------------- combine r-splits, apply gate, write wag (tf32-rounded) ----------------
__global__ void combine_kernel(const float* __restrict__ po, const float* __restrict__ pm,
                               const float* __restrict__ pl, const float* __restrict__ gate,
                               float* __restrict__ wag) {
    int idx = blockIdx.x * 256 + threadIdx.x;
    const int TOT = H_HEADS * T_TOK * KD;
    if (idx >= TOT) return;
    int c  = idx % KD;
    int ht = idx / KD;
    int tt = ht % T_TOK, h = ht / T_TOK;
    float m0 = pm[ht], m1 = pm[H_HEADS * T_TOK + ht];
    float mm = fmaxf(m0, m1);
    float s0 = __expf(m0 - mm), s1 = __expf(m1 - mm);
    float l = pl[ht] * s0 + pl[H_HEADS * T_TOK + ht] * s1;
    float o = (po[idx] * s0 + po[(size_t)H_HEADS * T_TOK * KD + idx] * s1) / l;
    float g = gate[(size_t)tt * C_DIM + h * KD + c];
    wag[(size_t)tt * C_DIM + h * KD + c] = to_tf32(o * g);
}

// ---------------- host launch ----------------
static float* sym(const void* s) {
    void* p = nullptr;
    cudaGetSymbolAddress(&p, s);
    return (float*)p;
}

extern "C" void kernel_launch(void* const* d_in, const int* in_sizes, int n_in,
                              void* d_out, int out_size) {
    const float* original   = (const float*)d_in[0];
    const float* resampled  = (const float*)d_in[1];
    const float* attn_mask  = (const float*)d_in[2];
    const float* qn_scale   = (const float*)d_in[5];
    const float* qn_offset  = (const float*)d_in[6];
    const float* dn_scale   = (const float*)d_in[7];
    const float* dn_offset  = (const float*)d_in[8];
    const float* query_w    = (const float*)d_in[9];
    const float* key_w      = (const float*)d_in[10];
    const float* value_w    = (const float*)d_in[11];
    const float* gating_w   = (const float*)d_in[12];
    const float* gating_b   = (const float*)d_in[13];
    const float* output_w   = (const float*)d_in[14];
    const float* output_b   = (const float*)d_in[15];
    const float* rt_ln_scale  = (const float*)d_in[16];
    const float* rt_ln_offset = (const float*)d_in[17];
    const float* rt_w1 = (const float*)d_in[18];
    const float* rt_b1 = (const float*)d_in[19];
    const float* rt_w2 = (const float*)d_in[20];
    const float* rt_b2 = (const float*)d_in[21];
    const float* ot_ln_scale  = (const float*)d_in[22];
    const float* ot_ln_offset = (const float*)d_in[23];
    const float* ot_w1 = (const float*)d_in[24];
    const float* ot_b1 = (const float*)d_in[25];
    const float* ot_w2 = (const float*)d_in[26];
    const float* ot_b2 = (const float*)d_in[27];

    float* out_res  = (float*)d_out;
    float* out_orig = out_res + (size_t)T_TOK * C_DIM;

    float* p_qin  = sym(g_qin);
    float* p_din  = sym(g_din);
    float* p_ln4  = sym(g_ln4);
    float* p_q    = sym(g_q);
    float* p_gate = sym(g_gate);
    float* p_k    = sym(g_k);
    float* p_v    = sym(g_v);
    float* p_wag  = sym(g_wag);
    float* p_ln3  = sym(g_ln3);
    float* p_h1   = sym(g_h1);
    float* p_h2   = sym(g_h2);
    float* p_wts  = sym(g_wts);
    float* p_po   = sym(g_po);
    float* p_pm   = sym(g_pm);
    float* p_pl   = sym(g_pl);

    const int gemm_smem  = STAGES * 2 * 4096 * 4;    // 98304
    const int flash_smem = FL_TOTAL * 4;             // 103424
    cudaFuncSetAttribute(gemm_tc, cudaFuncAttributeMaxDynamicSharedMemorySize, gemm_smem);
    cudaFuncSetAttribute(flash_kernel, cudaFuncAttributeMaxDynamicSharedMemorySize, flash_smem);

    const float inv_sqrt_kd = 0.14433756729740643f;

    // round weights to tf32 (cp.async path cannot round; truncation would bias ~1e-3)
    struct { const float* src; int off, n; } wl[9] = {
        {query_w,  OFF_QW,  147456}, {key_w,   OFF_KW,  147456},
        {value_w,  OFF_VW,  147456}, {gating_w, OFF_GW, 147456},
        {output_w, OFF_OW,  147456}, {rt_w1,   OFF_RT1, 589824},
        {rt_w2,    OFF_RT2, 589824}, {ot_w1,   OFF_OT1, 589824},
        {ot_w2,    OFF_OT2, 589824}
    };
    for (int i = 0; i < 9; i++) {
        int n4 = wl[i].n / 4;
        round4_kernel<<<(n4 + 255) / 256, 256>>>(wl[i].src, p_wts + wl[i].off, n4);
    }

    // LayerNorms
    ln_kernel<<<T_TOK, 128>>>(resampled, qn_scale, qn_offset, p_qin);
    ln_kernel<<<N_RES, 128>>>(original,  dn_scale, dn_offset, p_din);
    ln_kernel<<<N_RES, 128>>>(original,  ot_ln_scale, ot_ln_offset, p_ln4);

    // Projections
    gemm_tc<<<dim3(3, 4),  256, gemm_smem>>>(p_qin, p_wts + OFF_QW, p_q,    T_TOK, C_DIM, C_DIM, inv_sqrt_kd, nullptr,  ACT_NONE,    nullptr, 1);
    gemm_tc<<<dim3(3, 4),  256, gemm_smem>>>(p_qin, p_wts + OFF_GW, p_gate, T_TOK, C_DIM, C_DIM, 1.0f,        gating_b, ACT_SIGMOID, nullptr, 0);
    gemm_tc<<<dim3(3, 32), 256, gemm_smem>>>(p_din, p_wts + OFF_KW, p_k,    N_RES, C_DIM, C_DIM, 1.0f,        nullptr,  ACT_NONE,    nullptr, 1);
    gemm_tc<<<dim3(3, 32), 256, gemm_smem>>>(p_din, p_wts + OFF_VW, p_v,    N_RES, C_DIM, C_DIM, 1.0f,        nullptr,  ACT_NONE,    nullptr, 1);

    // Flash attention + combine
    flash_kernel<<<dim3(T_TOK / 64, H_HEADS, RSPLIT), 128, flash_smem>>>(
        p_q, p_k, p_v, attn_mask, p_po, p_pm, p_pl);
    combine_kernel<<<(H_HEADS * T_TOK * KD + 255) / 256, 256>>>(p_po, p_pm, p_pl, p_gate, p_wag);

    // Output projection + residual
    gemm_tc<<<dim3(3, 4), 256, gemm_smem>>>(p_wag, p_wts + OFF_OW, out_res, T_TOK, C_DIM, C_DIM, 1.0f, output_b, ACT_NONE, resampled, 0);

    // resampled transition
    ln_kernel<<<T_TOK, 128>>>(out_res, rt_ln_scale, rt_ln_offset, p_ln3);
    gemm_tc<<<dim3(12, 4), 256, gemm_smem>>>(p_ln3, p_wts + OFF_RT1, p_h1,    T_TOK, F_DIM, C_DIM, 1.0f, rt_b1, ACT_RELU, nullptr, 1);
    gemm_tc<<<dim3(3, 4),  256, gemm_smem>>>(p_h1,  p_wts + OFF_RT2, out_res, T_TOK, C_DIM, F_DIM, 1.0f, rt_b2, ACT_NONE, out_res, 0);

    // original transition
    gemm_tc<<<dim3(12, 32), 256, gemm_smem>>>(p_ln4, p_wts + OFF_OT1, p_h2,     N_RES, F_DIM, C_DIM, 1.0f, ot_b1, ACT_RELU, nullptr, 1);
    gemm_tc<<<dim3(3, 32),  256, gemm_smem>>>(p_h2,  p_wts + OFF_OT2, out_orig, N_RES, C_DIM, F_DIM, 1.0f, ot_b2, ACT_NONE, original, 0);
}

// round 5
// speedup vs baseline: 4.3055x; 1.2175x over previous
#include <cuda_runtime.h>
#include <math.h>

#define T_TOK 512
#define N_RES 4096
#define C_DIM 384
#define H_HEADS 8
#define KD 48
#define F_DIM 1536
#define LN_EPS 1e-5f
#define BIGF 1e9f
#define RSPLIT 4
#define RCHUNK 64
#define STAGES 3

// ---------------- scratch (device globals; no runtime alloc allowed) ----------------
__device__ float g_qin [T_TOK * C_DIM];
__device__ float g_din [N_RES * C_DIM];
__device__ float g_ln4 [N_RES * C_DIM];
__device__ float g_q   [T_TOK * C_DIM];
__device__ float g_gate[T_TOK * C_DIM];
__device__ float g_k   [N_RES * C_DIM];
__device__ float g_v   [N_RES * C_DIM];
__device__ float g_wag [T_TOK * C_DIM];
__device__ float g_ln3 [T_TOK * C_DIM];
__device__ float g_h1  [T_TOK * F_DIM];
__device__ float g_h2  [N_RES * F_DIM];
// tf32-rounded weights (concatenated, order: qw kw vw gw ow rt1 rt2 ot1 ot2)
#define OFF_QW  0
#define OFF_KW  147456
#define OFF_VW  294912
#define OFF_GW  442368
#define OFF_OW  589824
#define OFF_RT1 737280
#define OFF_RT2 1327104
#define OFF_OT1 1916928
#define OFF_OT2 2506752
#define WTS_TOTAL 3096576
__device__ float g_wts[WTS_TOTAL];
// flash partials
__device__ float g_po[RSPLIT * H_HEADS * T_TOK * KD];
__device__ float g_pm[RSPLIT * H_HEADS * T_TOK];
__device__ float g_pl[RSPLIT * H_HEADS * T_TOK];

__device__ __forceinline__ float to_tf32(float x) {
    asm("cvt.rna.tf32.f32 %0, %1;" : "=f"(x) : "f"(x));
    return x;
}

#define MMA_TF32(c, a, b) \
    asm volatile("mma.sync.aligned.m16n8k8.row.col.f32.tf32.tf32.f32 " \
        "{%0,%1,%2,%3}, {%4,%5,%6,%7}, {%8,%9}, {%0,%1,%2,%3};" \
        : "+f"((c)[0]), "+f"((c)[1]), "+f"((c)[2]), "+f"((c)[3]) \
        : "r"((a)[0]), "r"((a)[1]), "r"((a)[2]), "r"((a)[3]), \
          "r"((b)[0]), "r"((b)[1]))

__device__ __forceinline__ void cp16(float* dst, const float* src) {
    unsigned d = (unsigned)__cvta_generic_to_shared(dst);
    asm volatile("cp.async.ca.shared.global [%0], [%1], 16;" :: "r"(d), "l"(src));
}
#define CP_COMMIT() asm volatile("cp.async.commit_group;")
#define CP_WAIT(n)  asm volatile("cp.async.wait_group %0;" :: "n"(n))

// ---------------- fused weight rounding: all 9 weights in one launch ----------------
struct SrcPtrs { const float* p[9]; };
#define N4_TOTAL (WTS_TOTAL / 4)   // 774144

__global__ void round_all_kernel(SrcPtrs s, float* __restrict__ dst) {
    int i = blockIdx.x * blockDim.x + threadIdx.x;   // float4 index
    if (i >= N4_TOTAL) return;
    int seg, base;
    if (i < 184320) { seg = i / 36864; base = seg * 36864; }
    else            { seg = 5 + (i - 184320) / 147456; base = 184320 + (seg - 5) * 147456; }
    float4 v = reinterpret_cast<const float4*>(s.p[seg])[i - base];
    reinterpret_cast<float4*>(dst)[i] =
        make_float4(to_tf32(v.x), to_tf32(v.y), to_tf32(v.z), to_tf32(v.w));
}

// ---------------- LayerNorm core (one 128-thr block per row of 384) ----------------
__device__ __forceinline__ void ln_row(const float* __restrict__ xr,
                                       const float* __restrict__ scale,
                                       const float* __restrict__ offset,
                                       float* __restrict__ orow) {
    int t = threadIdx.x;
    float v0 = xr[t], v1 = xr[t + 128], v2 = xr[t + 256];
    float s  = v0 + v1 + v2;
    float s2 = v0 * v0 + v1 * v1 + v2 * v2;
    #pragma unroll
    for (int o = 16; o; o >>= 1) {
        s  += __shfl_down_sync(0xffffffffu, s,  o);
        s2 += __shfl_down_sync(0xffffffffu, s2, o);
    }
    __shared__ float sh[8];
    __shared__ float mu_s, rstd_s;
    int wid = t >> 5, lane = t & 31;
    if (lane == 0) { sh[wid] = s; sh[4 + wid] = s2; }
    __syncthreads();
    if (t == 0) {
        float ts  = sh[0] + sh[1] + sh[2] + sh[3];
        float ts2 = sh[4] + sh[5] + sh[6] + sh[7];
        float mu  = ts * (1.0f / C_DIM);
        float var = ts2 * (1.0f / C_DIM) - mu * mu;
        mu_s = mu; rstd_s = rsqrtf(var + LN_EPS);
    }
    __syncthreads();
    float mu = mu_s, rstd = rstd_s;
    orow[t]       = to_tf32(scale[t]       * (v0 - mu) * rstd + offset[t]);
    orow[t + 128] = to_tf32(scale[t + 128] * (v1 - mu) * rstd + offset[t + 128]);
    orow[t + 256] = to_tf32(scale[t + 256] * (v2 - mu) * rstd + offset[t + 256]);
}

__global__ void ln_kernel(const float* __restrict__ x, const float* __restrict__ scale,
                          const float* __restrict__ offset, float* __restrict__ out) {
    int row = blockIdx.x;
    ln_row(x + (size_t)row * C_DIM, scale, offset, out + (size_t)row * C_DIM);
}

// fused: rows [0,512) resampled->qin (qn), [512,4608) original->din (dn), [4608,8704) original->ln4 (ot_ln)
__global__ void ln_fused_kernel(const float* __restrict__ resampled, const float* __restrict__ original,
                                const float* __restrict__ qn_s, const float* __restrict__ qn_o,
                                const float* __restrict__ dn_s, const float* __restrict__ dn_o,
                                const float* __restrict__ ot_s, const float* __restrict__ ot_o,
                                float* __restrict__ qin, float* __restrict__ din, float* __restrict__ ln4) {
    int row = blockIdx.x;
    if (row < T_TOK) {
        ln_row(resampled + (size_t)row * C_DIM, qn_s, qn_o, qin + (size_t)row * C_DIM);
    } else if (row < T_TOK + N_RES) {
        int r = row - T_TOK;
        ln_row(original + (size_t)r * C_DIM, dn_s, dn_o, din + (size_t)r * C_DIM);
    } else {
        int r = row - T_TOK - N_RES;
        ln_row(original + (size_t)r * C_DIM, ot_s, ot_o, ln4 + (size_t)r * C_DIM);
    }
}

// ---------------- 128x128x32, 3-stage cp.async pipelined tf32 GEMM (dual-output capable) ----------------
#define ACT_NONE 0
#define ACT_RELU 1
#define ACT_SIGMOID 2

__global__ __launch_bounds__(256, 2) void gemm_tc(
    const float* __restrict__ A,
    const float* __restrict__ B0, float* __restrict__ C0, float alpha0,
    const float* __restrict__ bias0, int act0, const float* __restrict__ res0, int round0,
    const float* __restrict__ B1, float* __restrict__ C1, float alpha1,
    const float* __restrict__ bias1, int act1, const float* __restrict__ res1, int round1,
    int M, int N, int K, int halfX) {
    extern __shared__ float smg[];
    float* As = smg;
    float* Bs = smg + STAGES * 4096;

    int t = threadIdx.x;
    int bxx = blockIdx.x;
    const float* B = B0; float* C = C0; float alpha = alpha0;
    const float* bias = bias0; int act = act0; const float* residual = res0; int round_out = round0;
    if (bxx >= halfX) {
        bxx -= halfX;
        B = B1; C = C1; alpha = alpha1; bias = bias1; act = act1; residual = res1; round_out = round1;
    }
    int bm = blockIdx.y * 128, bn = bxx * 128;
    int wid = t >> 5, lane = t & 31, grp = lane >> 2, tig = lane & 3;
    int wm = (wid >> 2) * 64;
    int wn = (wid & 3) * 32;

    int a_dst[4], b_dst[4];
    size_t a_src[4], b_src[4];
    #pragma unroll
    for (int i = 0; i < 4; i++) {
        int idx = t + i * 256;
        int am = idx >> 3, af = idx & 7;
        a_dst[i] = (am * 8 + (af ^ (am & 7))) * 4;
        a_src[i] = (size_t)(bm + am) * K + af * 4;
        int bk = idx >> 5, bf = idx & 31;
        b_dst[i] = (bk * 32 + (bf ^ ((bk & 3) << 1))) * 4;
        b_src[i] = (size_t)bk * N + bn + bf * 4;
    }

    float acc[4][4][4];
    #pragma unroll
    for (int i = 0; i < 4; i++)
        #pragma unroll
        for (int j = 0; j < 4; j++)
            #pragma unroll
            for (int r = 0; r < 4; r++) acc[i][j][r] = 0.0f;

    int kTiles = K >> 5;

    #pragma unroll
    for (int pt = 0; pt < STAGES - 1; pt++) {
        float* ab = As + pt * 4096;
        float* bb = Bs + pt * 4096;
        #pragma unroll
        for (int i = 0; i < 4; i++) {
            cp16(ab + a_dst[i], A + a_src[i] + pt * 32);
            cp16(bb + b_dst[i], B + b_src[i] + (size_t)pt * 32 * N);
        }
        CP_COMMIT();
    }

    for (int kt = 0; kt < kTiles; kt++) {
        CP_WAIT(STAGES - 2);
        __syncthreads();
        int nt = kt + STAGES - 1;
        if (nt < kTiles) {
            int buf = nt % STAGES;
            float* ab = As + buf * 4096;
            float* bb = Bs + buf * 4096;
            #pragma unroll
            for (int i = 0; i < 4; i++) {
                cp16(ab + a_dst[i], A + a_src[i] + nt * 32);
                cp16(bb + b_dst[i], B + b_src[i] + (size_t)nt * 32 * N);
            }
        }
        CP_COMMIT();
        const float* as = As + (kt % STAGES) * 4096;
        const float* bs = Bs + (kt % STAGES) * 4096;
        #pragma unroll
        for (int s = 0; s < 4; s++) {
            int k0 = s * 8;
            unsigned af[4][4];
            #pragma unroll
            for (int fm = 0; fm < 4; fm++) {
                int m = wm + fm * 16 + grp;
                int swl = 4 * ((2 * s) ^ grp);
                int swh = 4 * ((2 * s + 1) ^ grp);
                af[fm][0] = __float_as_uint(as[m * 32 + tig + swl]);
                af[fm][1] = __float_as_uint(as[(m + 8) * 32 + tig + swl]);
                af[fm][2] = __float_as_uint(as[m * 32 + tig + swh]);
                af[fm][3] = __float_as_uint(as[(m + 8) * 32 + tig + swh]);
            }
            unsigned bf[4][2];
            #pragma unroll
            for (int fn = 0; fn < 4; fn++) {
                int n = wn + fn * 8 + grp;
                int col = (n & 3) + 4 * ((n >> 2) ^ (2 * tig));
                bf[fn][0] = __float_as_uint(bs[(k0 + tig) * 128 + col]);
                bf[fn][1] = __float_as_uint(bs[(k0 + 4 + tig) * 128 + col]);
            }
            #pragma unroll
            for (int fm = 0; fm < 4; fm++)
                #pragma unroll
                for (int fn = 0; fn < 4; fn++)
                    MMA_TF32(acc[fm][fn], af[fm], bf[fn]);
        }
        __syncthreads();
    }

    #pragma unroll
    for (int fm = 0; fm < 4; fm++) {
        #pragma unroll
        for (int fn = 0; fn < 4; fn++) {
            int m0 = bm + wm + fm * 16 + grp;
            int n  = bn + wn + fn * 8 + tig * 2;
            #pragma unroll
            for (int half = 0; half < 2; half++) {
                int m = m0 + half * 8;
                float x0 = acc[fm][fn][half * 2 + 0] * alpha;
                float x1 = acc[fm][fn][half * 2 + 1] * alpha;
                if (bias) { x0 += bias[n]; x1 += bias[n + 1]; }
                if (act == ACT_RELU) {
                    x0 = fmaxf(x0, 0.0f); x1 = fmaxf(x1, 0.0f);
                } else if (act == ACT_SIGMOID) {
                    x0 = 1.0f / (1.0f + __expf(-x0));
                    x1 = 1.0f / (1.0f + __expf(-x1));
                }
                if (residual) {
                    float2 r = *reinterpret_cast<const float2*>(&residual[(size_t)m * N + n]);
                    x0 += r.x; x1 += r.y;
                }
                if (round_out) { x0 = to_tf32(x0); x1 = to_tf32(x1); }
                *reinterpret_cast<float2*>(&C[(size_t)m * N + n]) = make_float2(x0, x1);
            }
        }
    }
}

// ---------------- flash attention: per block (64 t-rows, head, r-split) ----------------
#define QS_PITCH 52
#define VS_PITCH 56
#define MS_PITCH 68
#define FL_QS 0
#define FL_KS (64*52)
#define FL_VS (FL_KS + 2*64*52)
#define FL_MS (FL_VS + 2*64*56)
#define FL_TOTAL (FL_MS + 2*64*68)

__global__ __launch_bounds__(128) void flash_kernel(
    const float* __restrict__ q, const float* __restrict__ k,
    const float* __restrict__ v, const float* __restrict__ mask,
    float* __restrict__ po, float* __restrict__ pm, float* __restrict__ pl) {
    extern __shared__ float sm[];
    float* Qs = sm + FL_QS;
    int t = threadIdx.x;
    int wid = t >> 5, lane = t & 31, grp = lane >> 2, tig = lane & 3;
    int t0 = blockIdx.x * 64;
    int h  = blockIdx.y;
    int rsp = blockIdx.z;
    int rbase = rsp * (N_RES / RSPLIT);
    int wr = wid * 16;

    for (int i = t; i < 64 * 12; i += 128) {
        int r = i / 12, f = i % 12;
        float4 q4 = *reinterpret_cast<const float4*>(&q[(size_t)(t0 + r) * C_DIM + h * KD + f * 4]);
        *reinterpret_cast<float4*>(&Qs[r * QS_PITCH + f * 4]) = q4;
    }

    const int NCH = (N_RES / RSPLIT) / RCHUNK;   // 16

    auto issue = [&](int ch, int b) {
        int r0 = rbase + ch * RCHUNK;
        float* ks = sm + FL_KS + b * 64 * QS_PITCH;
        float* vs = sm + FL_VS + b * 64 * VS_PITCH;
        float* ms = sm + FL_MS + b * 64 * MS_PITCH;
        for (int i = t; i < 64 * 12; i += 128) {
            int r = i / 12, f = i % 12;
            size_t src = (size_t)(r0 + r) * C_DIM + h * KD + f * 4;
            cp16(&ks[r * QS_PITCH + f * 4], &k[src]);
            cp16(&vs[r * VS_PITCH + f * 4], &v[src]);
        }
        for (int i = t; i < 64 * 16; i += 128) {
            int rr = i / 16, f = i % 16;
            cp16(&ms[rr * MS_PITCH + f * 4],
                 &mask[((size_t)h * T_TOK + t0 + rr) * N_RES + r0 + f * 4]);
        }
    };

    issue(0, 0); CP_COMMIT();
    issue(1, 1); CP_COMMIT();

    float m_lo = -1e30f, m_hi = -1e30f, l_lo = 0.0f, l_hi = 0.0f;
    float acc_o[6][4];
    #pragma unroll
    for (int i = 0; i < 6; i++)
        #pragma unroll
        for (int e = 0; e < 4; e++) acc_o[i][e] = 0.0f;

    for (int ch = 0; ch < NCH; ch++) {
        int b = ch & 1;
        CP_WAIT(1);
        __syncthreads();
        float* ks = sm + FL_KS + b * 64 * QS_PITCH;
        float* vs = sm + FL_VS + b * 64 * VS_PITCH;
        float* ms = sm + FL_MS + b * 64 * MS_PITCH;

        float acc_s[8][4];
        #pragma unroll
        for (int fn = 0; fn < 8; fn++)
            #pragma unroll
            for (int e = 0; e < 4; e++) acc_s[fn][e] = 0.0f;
        #pragma unroll
        for (int s = 0; s < 6; s++) {
            int k0 = s * 8;
            unsigned a[4];
            a[0] = __float_as_uint(Qs[(wr + grp) * QS_PITCH + k0 + tig]);
            a[1] = __float_as_uint(Qs[(wr + grp + 8) * QS_PITCH + k0 + tig]);
            a[2] = __float_as_uint(Qs[(wr + grp) * QS_PITCH + k0 + 4 + tig]);
            a[3] = __float_as_uint(Qs[(wr + grp + 8) * QS_PITCH + k0 + 4 + tig]);
            #pragma unroll
            for (int fn = 0; fn < 8; fn++) {
                unsigned bb[2];
                bb[0] = __float_as_uint(ks[(fn * 8 + grp) * QS_PITCH + k0 + tig]);
                bb[1] = __float_as_uint(ks[(fn * 8 + grp) * QS_PITCH + k0 + 4 + tig]);
                MMA_TF32(acc_s[fn], a, bb);
            }
        }
        float mx_lo = -1e30f, mx_hi = -1e30f;
        #pragma unroll
        for (int fn = 0; fn < 8; fn++) {
            int col = fn * 8 + 2 * tig;
            float2 blo = *reinterpret_cast<float2*>(&ms[(wr + grp) * MS_PITCH + col]);
            float2 bhi = *reinterpret_cast<float2*>(&ms[(wr + grp + 8) * MS_PITCH + col]);
            acc_s[fn][0] += BIGF * (blo.x - 1.0f);
            acc_s[fn][1] += BIGF * (blo.y - 1.0f);
            acc_s[fn][2] += BIGF * (bhi.x - 1.0f);
            acc_s[fn][3] += BIGF * (bhi.y - 1.0f);
            mx_lo = fmaxf(mx_lo, fmaxf(acc_s[fn][0], acc_s[fn][1]));
            mx_hi = fmaxf(mx_hi, fmaxf(acc_s[fn][2], acc_s[fn][3]));
        }
        mx_lo = fmaxf(mx_lo, __shfl_xor_sync(0xffffffffu, mx_lo, 1));
        mx_lo = fmaxf(mx_lo, __shfl_xor_sync(0xffffffffu, mx_lo, 2));
        mx_hi = fmaxf(mx_hi, __shfl_xor_sync(0xffffffffu, mx_hi, 1));
        mx_hi = fmaxf(mx_hi, __shfl_xor_sync(0xffffffffu, mx_hi, 2));
        float mn_lo = fmaxf(m_lo, mx_lo), mn_hi = fmaxf(m_hi, mx_hi);
        float sc_lo = __expf(m_lo - mn_lo), sc_hi = __expf(m_hi - mn_hi);
        m_lo = mn_lo; m_hi = mn_hi;
        float rs_lo = 0.0f, rs_hi = 0.0f;
        #pragma unroll
        for (int fn = 0; fn < 8; fn++) {
            int col = fn * 8 + 2 * tig;
            float p0 = __expf(acc_s[fn][0] - mn_lo);
            float p1 = __expf(acc_s[fn][1] - mn_lo);
            float p2 = __expf(acc_s[fn][2] - mn_hi);
            float p3 = __expf(acc_s[fn][3] - mn_hi);
            rs_lo += p0 + p1; rs_hi += p2 + p3;
            *reinterpret_cast<float2*>(&ms[(wr + grp) * MS_PITCH + col]) =
                make_float2(to_tf32(p0), to_tf32(p1));
            *reinterpret_cast<float2*>(&ms[(wr + grp + 8) * MS_PITCH + col]) =
                make_float2(to_tf32(p2), to_tf32(p3));
        }
        rs_lo += __shfl_xor_sync(0xffffffffu, rs_lo, 1);
        rs_lo += __shfl_xor_sync(0xffffffffu, rs_lo, 2);
        rs_hi += __shfl_xor_sync(0xffffffffu, rs_hi, 1);
        rs_hi += __shfl_xor_sync(0xffffffffu, rs_hi, 2);
        l_lo = l_lo * sc_lo + rs_lo;
        l_hi = l_hi * sc_hi + rs_hi;
        #pragma unroll
        for (int fn = 0; fn < 6; fn++) {
            acc_o[fn][0] *= sc_lo; acc_o[fn][1] *= sc_lo;
            acc_o[fn][2] *= sc_hi; acc_o[fn][3] *= sc_hi;
        }
        __syncwarp();
        #pragma unroll
        for (int s = 0; s < 8; s++) {
            int k0 = s * 8;
            unsigned a[4];
            a[0] = __float_as_uint(ms[(wr + grp) * MS_PITCH + k0 + tig]);
            a[1] = __float_as_uint(ms[(wr + grp + 8) * MS_PITCH + k0 + tig]);
            a[2] = __float_as_uint(ms[(wr + grp) * MS_PITCH + k0 + 4 + tig]);
            a[3] = __float_as_uint(ms[(wr + grp + 8) * MS_PITCH + k0 + 4 + tig]);
            #pragma unroll
            for (int fn = 0; fn < 6; fn++) {
                unsigned bb[2];
                bb[0] = __float_as_uint(vs[(k0 + tig) * VS_PITCH + fn * 8 + grp]);
                bb[1] = __float_as_uint(vs[(k0 + 4 + tig) * VS_PITCH + fn * 8 + grp]);
                MMA_TF32(acc_o[fn], a, bb);
            }
        }
        __syncthreads();
        if (ch + 2 < NCH) issue(ch + 2, b);
        CP_COMMIT();
    }

    int row_lo = (rsp * H_HEADS + h) * T_TOK + t0 + wr + grp;
    int row_hi = row_lo + 8;
    #pragma unroll
    for (int fn = 0; fn < 6; fn++) {
        int c = fn * 8 + 2 * tig;
        *reinterpret_cast<float2*>(&po[(size_t)row_lo * KD + c]) =
            make_float2(acc_o[fn][0], acc_o[fn][1]);
        *reinterpret_cast<float2*>(&po[(size_t)row_hi * KD + c]) =
            make_float2(acc_o[fn][2], acc_o[fn][3]);
    }
    if (tig == 0) {
        pm[row_lo] = m_lo; pm[row_hi] = m_hi;
        pl[row_lo] = l_lo; pl[row_hi] = l_hi;
    }
}

// ---------------- combine r-splits, apply gate, write wag (tf32-rounded) ----------------
__global__ void combine_kernel(const float* __restrict__ po, const float* __restrict__ pm,
                               const float* __restrict__ pl, const float* __restrict__ gate,
                               float* __restrict__ wag) {
    int idx = blockIdx.x * 256 + threadIdx.x;
    const int TOT = H_HEADS * T_TOK * KD;
    const int HT  = H_HEADS * T_TOK;
    if (idx >= TOT) return;
    int c  = idx % KD;
    int ht = idx / KD;
    int tt = ht % T_TOK, h = ht / T_TOK;
    float mm = -1e30f;
    #pragma unroll
    for (int r = 0; r < RSPLIT; r++) mm = fmaxf(mm, pm[r * HT + ht]);
    float l = 0.0f, o = 0.0f;
    #pragma unroll
    for (int r = 0; r < RSPLIT; r++) {
        float s = __expf(pm[r * HT + ht] - mm);
        l += pl[r * HT + ht] * s;
        o += po[(size_t)r * TOT + idx] * s;
    }
    o /= l;
    float g = gate[(size_t)tt * C_DIM + h * KD + c];
    wag[(size_t)tt * C_DIM + h * KD + c] = to_tf32(o * g);
}

// ---------------- host launch ----------------
static float* sym(const void* s) {
    void* p = nullptr;
    cudaGetSymbolAddress(&p, s);
    return (float*)p;
}

extern "C" void kernel_launch(void* const* d_in, const int* in_sizes, int n_in,
                              void* d_out, int out_size) {
    const float* original   = (const float*)d_in[0];
    const float* resampled  = (const float*)d_in[1];
    const float* attn_mask  = (const float*)d_in[2];
    const float* qn_scale   = (const float*)d_in[5];
    const float* qn_offset  = (const float*)d_in[6];
    const float* dn_scale   = (const float*)d_in[7];
    const float* dn_offset  = (const float*)d_in[8];
    const float* query_w    = (const float*)d_in[9];
    const float* key_w      = (const float*)d_in[10];
    const float* value_w    = (const float*)d_in[11];
    const float* gating_w   = (const float*)d_in[12];
    const float* gating_b   = (const float*)d_in[13];
    const float* output_w   = (const float*)d_in[14];
    const float* output_b   = (const float*)d_in[15];
    const float* rt_ln_scale  = (const float*)d_in[16];
    const float* rt_ln_offset = (const float*)d_in[17];
    const float* rt_w1 = (const float*)d_in[18];
    const float* rt_b1 = (const float*)d_in[19];
    const float* rt_w2 = (const float*)d_in[20];
    const float* rt_b2 = (const float*)d_in[21];
    const float* ot_ln_scale  = (const float*)d_in[22];
    const float* ot_ln_offset = (const float*)d_in[23];
    const float* ot_w1 = (const float*)d_in[24];
    const float* ot_b1 = (const float*)d_in[25];
    const float* ot_w2 = (const float*)d_in[26];
    const float* ot_b2 = (const float*)d_in[27];

    float* out_res  = (float*)d_out;
    float* out_orig = out_res + (size_t)T_TOK * C_DIM;

    float* p_qin  = sym(g_qin);
    float* p_din  = sym(g_din);
    float* p_ln4  = sym(g_ln4);
    float* p_q    = sym(g_q);
    float* p_gate = sym(g_gate);
    float* p_k    = sym(g_k);
    float* p_v    = sym(g_v);
    float* p_wag  = sym(g_wag);
    float* p_ln3  = sym(g_ln3);
    float* p_h1   = sym(g_h1);
    float* p_h2   = sym(g_h2);
    float* p_wts  = sym(g_wts);
    float* p_po   = sym(g_po);
    float* p_pm   = sym(g_pm);
    float* p_pl   = sym(g_pl);

    const int gemm_smem  = STAGES * 2 * 4096 * 4;
    const int flash_smem = FL_TOTAL * 4;
    cudaFuncSetAttribute(gemm_tc, cudaFuncAttributeMaxDynamicSharedMemorySize, gemm_smem);
    cudaFuncSetAttribute(flash_kernel, cudaFuncAttributeMaxDynamicSharedMemorySize, flash_smem);

    const float inv_sqrt_kd = 0.14433756729740643f;
    const int BIG_HALF = 1 << 30;   // single-output mode

    // side stream + events for independent 'original' branch (created per call; never
    // destroyed mid-capture — leak is bounded by the few host calls the harness makes)
    cudaStream_t s2 = 0;
    cudaEvent_t ev0 = 0, ev1 = 0;
    cudaStreamCreateWithFlags(&s2, cudaStreamNonBlocking);
    cudaEventCreateWithFlags(&ev0, cudaEventDisableTiming);
    cudaEventCreateWithFlags(&ev1, cudaEventDisableTiming);
    bool fork_ok = (s2 != 0) && (ev0 != 0) && (ev1 != 0);

    // 1) round all weights to tf32 in one launch
    SrcPtrs sp;
    sp.p[0] = query_w;  sp.p[1] = key_w;  sp.p[2] = value_w;
    sp.p[3] = gating_w; sp.p[4] = output_w;
    sp.p[5] = rt_w1;    sp.p[6] = rt_w2;  sp.p[7] = ot_w1; sp.p[8] = ot_w2;
    round_all_kernel<<<(N4_TOTAL + 255) / 256, 256>>>(sp, p_wts);

    // 2) fused input LayerNorms
    ln_fused_kernel<<<T_TOK + 2 * N_RES, 128>>>(resampled, original,
        qn_scale, qn_offset, dn_scale, dn_offset, ot_ln_scale, ot_ln_offset,
        p_qin, p_din, p_ln4);

    // 3) fork: original-transition branch on s2 (independent of attention chain)
    cudaStream_t br = 0;
    if (fork_ok) {
        cudaEventRecord(ev0, 0);
        cudaStreamWaitEvent(s2, ev0, 0);
        br = s2;
    }
    gemm_tc<<<dim3(12, 32), 256, gemm_smem, br>>>(p_ln4,
        p_wts + OFF_OT1, p_h2, 1.0f, ot_b1, ACT_RELU, nullptr, 1,
        nullptr, nullptr, 0.0f, nullptr, 0, nullptr, 0,
        N_RES, F_DIM, C_DIM, BIG_HALF);
    gemm_tc<<<dim3(3, 32), 256, gemm_smem, br>>>(p_h2,
        p_wts + OFF_OT2, out_orig, 1.0f, ot_b2, ACT_NONE, original, 0,
        nullptr, nullptr, 0.0f, nullptr, 0, nullptr, 0,
        N_RES, C_DIM, F_DIM, BIG_HALF);
    if (fork_ok) cudaEventRecord(ev1, s2);

    // 4) main chain: projections (dual), flash, combine, out-proj, rt transition
    gemm_tc<<<dim3(6, 4), 256, gemm_smem>>>(p_qin,
        p_wts + OFF_QW, p_q, inv_sqrt_kd, nullptr, ACT_NONE, nullptr, 1,
        p_wts + OFF_GW, p_gate, 1.0f, gating_b, ACT_SIGMOID, nullptr, 0,
        T_TOK, C_DIM, C_DIM, 3);
    gemm_tc<<<dim3(6, 32), 256, gemm_smem>>>(p_din,
        p_wts + OFF_KW, p_k, 1.0f, nullptr, ACT_NONE, nullptr, 1,
        p_wts + OFF_VW, p_v, 1.0f, nullptr, ACT_NONE, nullptr, 1,
        N_RES, C_DIM, C_DIM, 3);

    flash_kernel<<<dim3(T_TOK / 64, H_HEADS, RSPLIT), 128, flash_smem>>>(
        p_q, p_k, p_v, attn_mask, p_po, p_pm, p_pl);
    combine_kernel<<<(H_HEADS * T_TOK * KD + 255) / 256, 256>>>(p_po, p_pm, p_pl, p_gate, p_wag);

    gemm_tc<<<dim3(3, 4), 256, gemm_smem>>>(p_wag,
        p_wts + OFF_OW, out_res, 1.0f, output_b, ACT_NONE, resampled, 0,
        nullptr, nullptr, 0.0f, nullptr, 0, nullptr, 0,
        T_TOK, C_DIM, C_DIM, BIG_HALF);

    ln_kernel<<<T_TOK, 128>>>(out_res, rt_ln_scale, rt_ln_offset, p_ln3);
    gemm_tc<<<dim3(12, 4), 256, gemm_smem>>>(p_ln3,
        p_wts + OFF_RT1, p_h1, 1.0f, rt_b1, ACT_RELU, nullptr, 1,
        nullptr, nullptr, 0.0f, nullptr, 0, nullptr, 0,
        T_TOK, F_DIM, C_DIM, BIG_HALF);
    gemm_tc<<<dim3(3, 4), 256, gemm_smem>>>(p_h1,
        p_wts + OFF_RT2, out_res, 1.0f, rt_b2, ACT_NONE, out_res, 0,
        nullptr, nullptr, 0.0f, nullptr, 0, nullptr, 0,
        T_TOK, C_DIM, F_DIM, BIG_HALF);

    // 5) join
    if (fork_ok) cudaStreamWaitEvent(0, ev1, 0);
}

// round 6
// speedup vs baseline: 5.1151x; 1.1880x over previous
#include <cuda_runtime.h>
#include <cuda_bf16.h>
#include <math.h>

#define T_TOK 512
#define N_RES 4096
#define C_DIM 384
#define H_HEADS 8
#define KD 48
#define F_DIM 1536
#define LN_EPS 1e-5f
#define BIGF 1e9f
#define RSPLIT 4
#define RCHUNK 64
#define STAGES 3

typedef __nv_bfloat16 bf16;

// ---------------- scratch (device globals) ----------------
__device__ bf16  g_qin [T_TOK * C_DIM];
__device__ bf16  g_din [N_RES * C_DIM];
__device__ bf16  g_ln4 [N_RES * C_DIM];
__device__ float g_q   [T_TOK * C_DIM];
__device__ float g_gate[T_TOK * C_DIM];
__device__ float g_k   [N_RES * C_DIM];
__device__ float g_v   [N_RES * C_DIM];
__device__ bf16  g_wag [T_TOK * C_DIM];
__device__ bf16  g_ln3 [T_TOK * C_DIM];
__device__ bf16  g_h1  [T_TOK * F_DIM];
__device__ bf16  g_h2  [N_RES * F_DIM];
// bf16 TRANSPOSED weights Wt[N][K] (element offsets)
#define OFF_QW  0
#define OFF_KW  147456
#define OFF_VW  294912
#define OFF_GW  442368
#define OFF_OW  589824
#define OFF_RT1 737280
#define OFF_RT2 1327104
#define OFF_OT1 1916928
#define OFF_OT2 2506752
#define WTS_TOTAL 3096576
__device__ bf16 g_wts[WTS_TOTAL];
// flash partials
__device__ float g_po[RSPLIT * H_HEADS * T_TOK * KD];
__device__ float g_pm[RSPLIT * H_HEADS * T_TOK];
__device__ float g_pl[RSPLIT * H_HEADS * T_TOK];

__device__ __forceinline__ float to_tf32(float x) {
    asm("cvt.rna.tf32.f32 %0, %1;" : "=f"(x) : "f"(x));
    return x;
}

#define MMA_TF32(c, a, b) \
    asm volatile("mma.sync.aligned.m16n8k8.row.col.f32.tf32.tf32.f32 " \
        "{%0,%1,%2,%3}, {%4,%5,%6,%7}, {%8,%9}, {%0,%1,%2,%3};" \
        : "+f"((c)[0]), "+f"((c)[1]), "+f"((c)[2]), "+f"((c)[3]) \
        : "r"((a)[0]), "r"((a)[1]), "r"((a)[2]), "r"((a)[3]), \
          "r"((b)[0]), "r"((b)[1]))

#define MMA_BF16(c, a, b) \
    asm volatile("mma.sync.aligned.m16n8k16.row.col.f32.bf16.bf16.f32 " \
        "{%0,%1,%2,%3}, {%4,%5,%6,%7}, {%8,%9}, {%0,%1,%2,%3};" \
        : "+f"((c)[0]), "+f"((c)[1]), "+f"((c)[2]), "+f"((c)[3]) \
        : "r"((a)[0]), "r"((a)[1]), "r"((a)[2]), "r"((a)[3]), \
          "r"((b)[0]), "r"((b)[1]))

__device__ __forceinline__ void cp16(void* dst, const void* src) {
    unsigned d = (unsigned)__cvta_generic_to_shared(dst);
    asm volatile("cp.async.ca.shared.global [%0], [%1], 16;" :: "r"(d), "l"(src));
}
#define CP_COMMIT() asm volatile("cp.async.commit_group;")
#define CP_WAIT(n)  asm volatile("cp.async.wait_group %0;" :: "n"(n))

// ---------------- weight transpose + bf16 convert: W[K][N] fp32 -> Wt[N][K] bf16 ----------------
struct SrcPtrs { const float* p[9]; };

__global__ __launch_bounds__(256) void wt_kernel(SrcPtrs s, bf16* __restrict__ dst) {
    const int segK[9]   = {384, 384, 384, 384, 384, 384, 1536, 384, 1536};
    const int segN[9]   = {384, 384, 384, 384, 384, 1536, 384, 1536, 384};
    const int segOff[9] = {OFF_QW, OFF_KW, OFF_VW, OFF_GW, OFF_OW, OFF_RT1, OFF_RT2, OFF_OT1, OFF_OT2};
    const int cum[10]   = {0, 144, 288, 432, 576, 720, 1296, 1872, 2448, 3024};
    int b = blockIdx.x;
    int seg = 0;
    #pragma unroll
    for (int i = 1; i < 9; i++) if (b >= cum[i]) seg = i;
    int tile = b - cum[seg];
    int K = segK[seg], N = segN[seg];
    int ntn = N >> 5;
    int k0 = (tile / ntn) * 32, n0 = (tile % ntn) * 32;
    const float* src = s.p[seg];

    __shared__ float smt[32][33];
    int t = threadIdx.x;
    int r = t >> 3, c4 = (t & 7) * 4;
    float4 v = *reinterpret_cast<const float4*>(&src[(size_t)(k0 + r) * N + n0 + c4]);
    smt[r][c4 + 0] = v.x; smt[r][c4 + 1] = v.y;
    smt[r][c4 + 2] = v.z; smt[r][c4 + 3] = v.w;
    __syncthreads();
    int n = t >> 3, k4 = (t & 7) * 4;
    __nv_bfloat162 lo = __floats2bfloat162_rn(smt[k4 + 0][n], smt[k4 + 1][n]);
    __nv_bfloat162 hi = __floats2bfloat162_rn(smt[k4 + 2][n], smt[k4 + 3][n]);
    bf16* d = dst + segOff[seg] + (size_t)(n0 + n) * K + k0 + k4;
    *reinterpret_cast<__nv_bfloat162*>(d)     = lo;
    *reinterpret_cast<__nv_bfloat162*>(d + 2) = hi;
}

// ---------------- LayerNorm core: one 128-thr block per row of 384, bf16 output ----------------
__device__ __forceinline__ void ln_row(const float* __restrict__ xr,
                                       const float* __restrict__ scale,
                                       const float* __restrict__ offset,
                                       bf16* __restrict__ orow) {
    int t = threadIdx.x;
    float v0 = xr[t], v1 = xr[t + 128], v2 = xr[t + 256];
    float s  = v0 + v1 + v2;
    float s2 = v0 * v0 + v1 * v1 + v2 * v2;
    #pragma unroll
    for (int o = 16; o; o >>= 1) {
        s  += __shfl_down_sync(0xffffffffu, s,  o);
        s2 += __shfl_down_sync(0xffffffffu, s2, o);
    }
    __shared__ float sh[8];
    __shared__ float mu_s, rstd_s;
    int wid = t >> 5, lane = t & 31;
    if (lane == 0) { sh[wid] = s; sh[4 + wid] = s2; }
    __syncthreads();
    if (t == 0) {
        float ts  = sh[0] + sh[1] + sh[2] + sh[3];
        float ts2 = sh[4] + sh[5] + sh[6] + sh[7];
        float mu  = ts * (1.0f / C_DIM);
        float var = ts2 * (1.0f / C_DIM) - mu * mu;
        mu_s = mu; rstd_s = rsqrtf(var + LN_EPS);
    }
    __syncthreads();
    float mu = mu_s, rstd = rstd_s;
    orow[t]       = __float2bfloat16_rn(scale[t]       * (v0 - mu) * rstd + offset[t]);
    orow[t + 128] = __float2bfloat16_rn(scale[t + 128] * (v1 - mu) * rstd + offset[t + 128]);
    orow[t + 256] = __float2bfloat16_rn(scale[t + 256] * (v2 - mu) * rstd + offset[t + 256]);
}

__global__ void ln_kernel(const float* __restrict__ x, const float* __restrict__ scale,
                          const float* __restrict__ offset, bf16* __restrict__ out) {
    int row = blockIdx.x;
    ln_row(x + (size_t)row * C_DIM, scale, offset, out + (size_t)row * C_DIM);
}

__global__ void ln_fused_kernel(const float* __restrict__ resampled, const float* __restrict__ original,
                                const float* __restrict__ qn_s, const float* __restrict__ qn_o,
                                const float* __restrict__ dn_s, const float* __restrict__ dn_o,
                                const float* __restrict__ ot_s, const float* __restrict__ ot_o,
                                bf16* __restrict__ qin, bf16* __restrict__ din, bf16* __restrict__ ln4) {
    int row = blockIdx.x;
    if (row < T_TOK) {
        ln_row(resampled + (size_t)row * C_DIM, qn_s, qn_o, qin + (size_t)row * C_DIM);
    } else if (row < T_TOK + N_RES) {
        int r = row - T_TOK;
        ln_row(original + (size_t)r * C_DIM, dn_s, dn_o, din + (size_t)r * C_DIM);
    } else {
        int r = row - T_TOK - N_RES;
        ln_row(original + (size_t)r * C_DIM, ot_s, ot_o, ln4 + (size_t)r * C_DIM);
    }
}

// ---------------- 128x128x64 bf16 GEMM, 3-stage cp.async, m16n8k16 ----------------
// A[M][K] bf16, B = Wt[N][K] bf16. out modes: 0=f32(+res), 1=f32 tf32-rounded(+res), 2=bf16
#define ACT_NONE 0
#define ACT_RELU 1
#define ACT_SIGMOID 2

__global__ __launch_bounds__(256, 2) void gemm_bf(
    const bf16* __restrict__ A,
    const bf16* __restrict__ B0, void* __restrict__ C0v, float alpha0,
    const float* __restrict__ bias0, int act0, const float* __restrict__ res0, int mode0,
    const bf16* __restrict__ B1, void* __restrict__ C1v, float alpha1,
    const float* __restrict__ bias1, int act1, const float* __restrict__ res1, int mode1,
    int M, int N, int K, int halfX) {
    extern __shared__ bf16 smg[];
    bf16* As = smg;                       // STAGES * 8192 bf16
    bf16* Bs = smg + STAGES * 8192;

    int t = threadIdx.x;
    int bxx = blockIdx.x;
    const bf16* B = B0; void* Cv = C0v; float alpha = alpha0;
    const float* bias = bias0; int act = act0; const float* residual = res0; int mode = mode0;
    if (bxx >= halfX) {
        bxx -= halfX;
        B = B1; Cv = C1v; alpha = alpha1; bias = bias1; act = act1; residual = res1; mode = mode1;
    }
    int bm = blockIdx.y * 128, bn = bxx * 128;
    int wid = t >> 5, lane = t & 31, grp = lane >> 2, tig = lane & 3;
    int wm = (wid >> 2) * 64;
    int wn = (wid & 3) * 32;

    // load mapping: 1024 granules (16B = 8 bf16) per tile; thread i-th granule
    int a_dst[4], b_dst[4];       // bf16 element offsets into a stage
    size_t a_src[4], b_src[4];    // bf16 element offsets into global (+= kt*64)
    #pragma unroll
    for (int i = 0; i < 4; i++) {
        int idx = t + i * 256;
        int m = idx >> 3, g = idx & 7;
        a_dst[i] = (m * 8 + (g ^ (m & 7))) * 8;
        a_src[i] = (size_t)(bm + m) * K + g * 8;
        b_dst[i] = a_dst[i];
        b_src[i] = (size_t)(bn + m) * K + g * 8;
    }

    float acc[4][4][4];
    #pragma unroll
    for (int i = 0; i < 4; i++)
        #pragma unroll
        for (int j = 0; j < 4; j++)
            #pragma unroll
            for (int r = 0; r < 4; r++) acc[i][j][r] = 0.0f;

    int kTiles = K >> 6;

    #pragma unroll
    for (int pt = 0; pt < STAGES - 1; pt++) {
        bf16* ab = As + pt * 8192;
        bf16* bb = Bs + pt * 8192;
        #pragma unroll
        for (int i = 0; i < 4; i++) {
            cp16(ab + a_dst[i], A + a_src[i] + pt * 64);
            cp16(bb + b_dst[i], B + b_src[i] + pt * 64);
        }
        CP_COMMIT();
    }

    for (int kt = 0; kt < kTiles; kt++) {
        CP_WAIT(STAGES - 2);
        __syncthreads();
        int nt = kt + STAGES - 1;
        if (nt < kTiles) {
            int buf = nt % STAGES;
            bf16* ab = As + buf * 8192;
            bf16* bb = Bs + buf * 8192;
            #pragma unroll
            for (int i = 0; i < 4; i++) {
                cp16(ab + a_dst[i], A + a_src[i] + nt * 64);
                cp16(bb + b_dst[i], B + b_src[i] + nt * 64);
            }
        }
        CP_COMMIT();
        const bf16* as = As + (kt % STAGES) * 8192;
        const bf16* bs = Bs + (kt % STAGES) * 8192;
        #pragma unroll
        for (int s = 0; s < 4; s++) {           // 4 x k16 steps
            unsigned af[4][4];
            #pragma unroll
            for (int fm = 0; fm < 4; fm++) {
                int m = wm + fm * 16 + grp;
                int g0 = (2 * s) ^ (m & 7), g1 = (2 * s + 1) ^ (m & 7);
                af[fm][0] = *reinterpret_cast<const unsigned*>(as + m * 64 + g0 * 8 + tig * 2);
                af[fm][1] = *reinterpret_cast<const unsigned*>(as + (m + 8) * 64 + g0 * 8 + tig * 2);
                af[fm][2] = *reinterpret_cast<const unsigned*>(as + m * 64 + g1 * 8 + tig * 2);
                af[fm][3] = *reinterpret_cast<const unsigned*>(as + (m + 8) * 64 + g1 * 8 + tig * 2);
            }
            unsigned bf[4][2];
            #pragma unroll
            for (int fn = 0; fn < 4; fn++) {
                int n = wn + fn * 8 + grp;
                int g0 = (2 * s) ^ (n & 7), g1 = (2 * s + 1) ^ (n & 7);
                bf[fn][0] = *reinterpret_cast<const unsigned*>(bs + n * 64 + g0 * 8 + tig * 2);
                bf[fn][1] = *reinterpret_cast<const unsigned*>(bs + n * 64 + g1 * 8 + tig * 2);
            }
            #pragma unroll
            for (int fm = 0; fm < 4; fm++)
                #pragma unroll
                for (int fn = 0; fn < 4; fn++)
                    MMA_BF16(acc[fm][fn], af[fm], bf[fn]);
        }
        __syncthreads();
    }

    #pragma unroll
    for (int fm = 0; fm < 4; fm++) {
        #pragma unroll
        for (int fn = 0; fn < 4; fn++) {
            int m0 = bm + wm + fm * 16 + grp;
            int n  = bn + wn + fn * 8 + tig * 2;
            #pragma unroll
            for (int half = 0; half < 2; half++) {
                int m = m0 + half * 8;
                float x0 = acc[fm][fn][half * 2 + 0] * alpha;
                float x1 = acc[fm][fn][half * 2 + 1] * alpha;
                if (bias) { x0 += bias[n]; x1 += bias[n + 1]; }
                if (act == ACT_RELU) {
                    x0 = fmaxf(x0, 0.0f); x1 = fmaxf(x1, 0.0f);
                } else if (act == ACT_SIGMOID) {
                    x0 = 1.0f / (1.0f + __expf(-x0));
                    x1 = 1.0f / (1.0f + __expf(-x1));
                }
                if (mode == 2) {
                    bf16* Cb = (bf16*)Cv;
                    *reinterpret_cast<__nv_bfloat162*>(&Cb[(size_t)m * N + n]) =
                        __floats2bfloat162_rn(x0, x1);
                } else {
                    float* Cf = (float*)Cv;
                    if (residual) {
                        float2 r = *reinterpret_cast<const float2*>(&residual[(size_t)m * N + n]);
                        x0 += r.x; x1 += r.y;
                    }
                    if (mode == 1) { x0 = to_tf32(x0); x1 = to_tf32(x1); }
                    *reinterpret_cast<float2*>(&Cf[(size_t)m * N + n]) = make_float2(x0, x1);
                }
            }
        }
    }
}

// ---------------- flash attention (tf32, unchanged) ----------------
#define QS_PITCH 52
#define VS_PITCH 56
#define MS_PITCH 68
#define FL_QS 0
#define FL_KS (64*52)
#define FL_VS (FL_KS + 2*64*52)
#define FL_MS (FL_VS + 2*64*56)
#define FL_TOTAL (FL_MS + 2*64*68)

__global__ __launch_bounds__(128) void flash_kernel(
    const float* __restrict__ q, const float* __restrict__ k,
    const float* __restrict__ v, const float* __restrict__ mask,
    float* __restrict__ po, float* __restrict__ pm, float* __restrict__ pl) {
    extern __shared__ float sm[];
    float* Qs = sm + FL_QS;
    int t = threadIdx.x;
    int wid = t >> 5, lane = t & 31, grp = lane >> 2, tig = lane & 3;
    int t0 = blockIdx.x * 64;
    int h  = blockIdx.y;
    int rsp = blockIdx.z;
    int rbase = rsp * (N_RES / RSPLIT);
    int wr = wid * 16;

    for (int i = t; i < 64 * 12; i += 128) {
        int r = i / 12, f = i % 12;
        float4 q4 = *reinterpret_cast<const float4*>(&q[(size_t)(t0 + r) * C_DIM + h * KD + f * 4]);
        *reinterpret_cast<float4*>(&Qs[r * QS_PITCH + f * 4]) = q4;
    }

    const int NCH = (N_RES / RSPLIT) / RCHUNK;   // 16

    auto issue = [&](int ch, int b) {
        int r0 = rbase + ch * RCHUNK;
        float* ks = sm + FL_KS + b * 64 * QS_PITCH;
        float* vs = sm + FL_VS + b * 64 * VS_PITCH;
        float* ms = sm + FL_MS + b * 64 * MS_PITCH;
        for (int i = t; i < 64 * 12; i += 128) {
            int r = i / 12, f = i % 12;
            size_t src = (size_t)(r0 + r) * C_DIM + h * KD + f * 4;
            cp16(&ks[r * QS_PITCH + f * 4], &k[src]);
            cp16(&vs[r * VS_PITCH + f * 4], &v[src]);
        }
        for (int i = t; i < 64 * 16; i += 128) {
            int rr = i / 16, f = i % 16;
            cp16(&ms[rr * MS_PITCH + f * 4],
                 &mask[((size_t)h * T_TOK + t0 + rr) * N_RES + r0 + f * 4]);
        }
    };

    issue(0, 0); CP_COMMIT();
    issue(1, 1); CP_COMMIT();

    float m_lo = -1e30f, m_hi = -1e30f, l_lo = 0.0f, l_hi = 0.0f;
    float acc_o[6][4];
    #pragma unroll
    for (int i = 0; i < 6; i++)
        #pragma unroll
        for (int e = 0; e < 4; e++) acc_o[i][e] = 0.0f;

    for (int ch = 0; ch < NCH; ch++) {
        int b = ch & 1;
        CP_WAIT(1);
        __syncthreads();
        float* ks = sm + FL_KS + b * 64 * QS_PITCH;
        float* vs = sm + FL_VS + b * 64 * VS_PITCH;
        float* ms = sm + FL_MS + b * 64 * MS_PITCH;

        float acc_s[8][4];
        #pragma unroll
        for (int fn = 0; fn < 8; fn++)
            #pragma unroll
            for (int e = 0; e < 4; e++) acc_s[fn][e] = 0.0f;
        #pragma unroll
        for (int s = 0; s < 6; s++) {
            int k0 = s * 8;
            unsigned a[4];
            a[0] = __float_as_uint(Qs[(wr + grp) * QS_PITCH + k0 + tig]);
            a[1] = __float_as_uint(Qs[(wr + grp + 8) * QS_PITCH + k0 + tig]);
            a[2] = __float_as_uint(Qs[(wr + grp) * QS_PITCH + k0 + 4 + tig]);
            a[3] = __float_as_uint(Qs[(wr + grp + 8) * QS_PITCH + k0 + 4 + tig]);
            #pragma unroll
            for (int fn = 0; fn < 8; fn++) {
                unsigned bb[2];
                bb[0] = __float_as_uint(ks[(fn * 8 + grp) * QS_PITCH + k0 + tig]);
                bb[1] = __float_as_uint(ks[(fn * 8 + grp) * QS_PITCH + k0 + 4 + tig]);
                MMA_TF32(acc_s[fn], a, bb);
            }
        }
        float mx_lo = -1e30f, mx_hi = -1e30f;
        #pragma unroll
        for (int fn = 0; fn < 8; fn++) {
            int col = fn * 8 + 2 * tig;
            float2 blo = *reinterpret_cast<float2*>(&ms[(wr + grp) * MS_PITCH + col]);
            float2 bhi = *reinterpret_cast<float2*>(&ms[(wr + grp + 8) * MS_PITCH + col]);
            acc_s[fn][0] += BIGF * (blo.x - 1.0f);
            acc_s[fn][1] += BIGF * (blo.y - 1.0f);
            acc_s[fn][2] += BIGF * (bhi.x - 1.0f);
            acc_s[fn][3] += BIGF * (bhi.y - 1.0f);
            mx_lo = fmaxf(mx_lo, fmaxf(acc_s[fn][0], acc_s[fn][1]));
            mx_hi = fmaxf(mx_hi, fmaxf(acc_s[fn][2], acc_s[fn][3]));
        }
        mx_lo = fmaxf(mx_lo, __shfl_xor_sync(0xffffffffu, mx_lo, 1));
        mx_lo = fmaxf(mx_lo, __shfl_xor_sync(0xffffffffu, mx_lo, 2));
        mx_hi = fmaxf(mx_hi, __shfl_xor_sync(0xffffffffu, mx_hi, 1));
        mx_hi = fmaxf(mx_hi, __shfl_xor_sync(0xffffffffu, mx_hi, 2));
        float mn_lo = fmaxf(m_lo, mx_lo), mn_hi = fmaxf(m_hi, mx_hi);
        float sc_lo = __expf(m_lo - mn_lo), sc_hi = __expf(m_hi - mn_hi);
        m_lo = mn_lo; m_hi = mn_hi;
        float rs_lo = 0.0f, rs_hi = 0.0f;
        #pragma unroll
        for (int fn = 0; fn < 8; fn++) {
            int col = fn * 8 + 2 * tig;
            float p0 = __expf(acc_s[fn][0] - mn_lo);
            float p1 = __expf(acc_s[fn][1] - mn_lo);
            float p2 = __expf(acc_s[fn][2] - mn_hi);
            float p3 = __expf(acc_s[fn][3] - mn_hi);
            rs_lo += p0 + p1; rs_hi += p2 + p3;
            *reinterpret_cast<float2*>(&ms[(wr + grp) * MS_PITCH + col]) =
                make_float2(to_tf32(p0), to_tf32(p1));
            *reinterpret_cast<float2*>(&ms[(wr + grp + 8) * MS_PITCH + col]) =
                make_float2(to_tf32(p2), to_tf32(p3));
        }
        rs_lo += __shfl_xor_sync(0xffffffffu, rs_lo, 1);
        rs_lo += __shfl_xor_sync(0xffffffffu, rs_lo, 2);
        rs_hi += __shfl_xor_sync(0xffffffffu, rs_hi, 1);
        rs_hi += __shfl_xor_sync(0xffffffffu, rs_hi, 2);
        l_lo = l_lo * sc_lo + rs_lo;
        l_hi = l_hi * sc_hi + rs_hi;
        #pragma unroll
        for (int fn = 0; fn < 6; fn++) {
            acc_o[fn][0] *= sc_lo; acc_o[fn][1] *= sc_lo;
            acc_o[fn][2] *= sc_hi; acc_o[fn][3] *= sc_hi;
        }
        __syncwarp();
        #pragma unroll
        for (int s = 0; s < 8; s++) {
            int k0 = s * 8;
            unsigned a[4];
            a[0] = __float_as_uint(ms[(wr + grp) * MS_PITCH + k0 + tig]);
            a[1] = __float_as_uint(ms[(wr + grp + 8) * MS_PITCH + k0 + tig]);
            a[2] = __float_as_uint(ms[(wr + grp) * MS_PITCH + k0 + 4 + tig]);
            a[3] = __float_as_uint(ms[(wr + grp + 8) * MS_PITCH + k0 + 4 + tig]);
            #pragma unroll
            for (int fn = 0; fn < 6; fn++) {
                unsigned bb[2];
                bb[0] = __float_as_uint(vs[(k0 + tig) * VS_PITCH + fn * 8 + grp]);
                bb[1] = __float_as_uint(vs[(k0 + 4 + tig) * VS_PITCH + fn * 8 + grp]);
                MMA_TF32(acc_o[fn], a, bb);
            }
        }
        __syncthreads();
        if (ch + 2 < NCH) issue(ch + 2, b);
        CP_COMMIT();
    }

    int row_lo = (rsp * H_HEADS + h) * T_TOK + t0 + wr + grp;
    int row_hi = row_lo + 8;
    #pragma unroll
    for (int fn = 0; fn < 6; fn++) {
        int c = fn * 8 + 2 * tig;
        *reinterpret_cast<float2*>(&po[(size_t)row_lo * KD + c]) =
            make_float2(acc_o[fn][0], acc_o[fn][1]);
        *reinterpret_cast<float2*>(&po[(size_t)row_hi * KD + c]) =
            make_float2(acc_o[fn][2], acc_o[fn][3]);
    }
    if (tig == 0) {
        pm[row_lo] = m_lo; pm[row_hi] = m_hi;
        pl[row_lo] = l_lo; pl[row_hi] = l_hi;
    }
}

// ---------------- combine r-splits, apply gate, write wag bf16 ----------------
__global__ void combine_kernel(const float* __restrict__ po, const float* __restrict__ pm,
                               const float* __restrict__ pl, const float* __restrict__ gate,
                               bf16* __restrict__ wag) {
    int idx = blockIdx.x * 256 + threadIdx.x;
    const int TOT = H_HEADS * T_TOK * KD;
    const int HT  = H_HEADS * T_TOK;
    if (idx >= TOT) return;
    int c  = idx % KD;
    int ht = idx / KD;
    int tt = ht % T_TOK, h = ht / T_TOK;
    float mm = -1e30f;
    #pragma unroll
    for (int r = 0; r < RSPLIT; r++) mm = fmaxf(mm, pm[r * HT + ht]);
    float l = 0.0f, o = 0.0f;
    #pragma unroll
    for (int r = 0; r < RSPLIT; r++) {
        float s = __expf(pm[r * HT + ht] - mm);
        l += pl[r * HT + ht] * s;
        o += po[(size_t)r * TOT + idx] * s;
    }
    o /= l;
    float g = gate[(size_t)tt * C_DIM + h * KD + c];
    wag[(size_t)tt * C_DIM + h * KD + c] = __float2bfloat16_rn(o * g);
}

// ---------------- host launch ----------------
static void* symv(const void* s) {
    void* p = nullptr;
    cudaGetSymbolAddress(&p, s);
    return p;
}

extern "C" void kernel_launch(void* const* d_in, const int* in_sizes, int n_in,
                              void* d_out, int out_size) {
    const float* original   = (const float*)d_in[0];
    const float* resampled  = (const float*)d_in[1];
    const float* attn_mask  = (const float*)d_in[2];
    const float* qn_scale   = (const float*)d_in[5];
    const float* qn_offset  = (const float*)d_in[6];
    const float* dn_scale   = (const float*)d_in[7];
    const float* dn_offset  = (const float*)d_in[8];
    const float* query_w    = (const float*)d_in[9];
    const float* key_w      = (const float*)d_in[10];
    const float* value_w    = (const float*)d_in[11];
    const float* gating_w   = (const float*)d_in[12];
    const float* gating_b   = (const float*)d_in[13];
    const float* output_w   = (const float*)d_in[14];
    const float* output_b   = (const float*)d_in[15];
    const float* rt_ln_scale  = (const float*)d_in[16];
    const float* rt_ln_offset = (const float*)d_in[17];
    const float* rt_w1 = (const float*)d_in[18];
    const float* rt_b1 = (const float*)d_in[19];
    const float* rt_w2 = (const float*)d_in[20];
    const float* rt_b2 = (const float*)d_in[21];
    const float* ot_ln_scale  = (const float*)d_in[22];
    const float* ot_ln_offset = (const float*)d_in[23];
    const float* ot_w1 = (const float*)d_in[24];
    const float* ot_b1 = (const float*)d_in[25];
    const float* ot_w2 = (const float*)d_in[26];
    const float* ot_b2 = (const float*)d_in[27];

    float* out_res  = (float*)d_out;
    float* out_orig = out_res + (size_t)T_TOK * C_DIM;

    bf16*  p_qin  = (bf16*)symv(g_qin);
    bf16*  p_din  = (bf16*)symv(g_din);
    bf16*  p_ln4  = (bf16*)symv(g_ln4);
    float* p_q    = (float*)symv(g_q);
    float* p_gate = (float*)symv(g_gate);
    float* p_k    = (float*)symv(g_k);
    float* p_v    = (float*)symv(g_v);
    bf16*  p_wag  = (bf16*)symv(g_wag);
    bf16*  p_ln3  = (bf16*)symv(g_ln3);
    bf16*  p_h1   = (bf16*)symv(g_h1);
    bf16*  p_h2   = (bf16*)symv(g_h2);
    bf16*  p_wts  = (bf16*)symv(g_wts);
    float* p_po   = (float*)symv(g_po);
    float* p_pm   = (float*)symv(g_pm);
    float* p_pl   = (float*)symv(g_pl);

    const int gemm_smem  = STAGES * 2 * 8192 * 2;   // 98304 bytes
    const int flash_smem = FL_TOTAL * 4;
    cudaFuncSetAttribute(gemm_bf, cudaFuncAttributeMaxDynamicSharedMemorySize, gemm_smem);
    cudaFuncSetAttribute(flash_kernel, cudaFuncAttributeMaxDynamicSharedMemorySize, flash_smem);

    const float inv_sqrt_kd = 0.14433756729740643f;
    const int BIG_HALF = 1 << 30;

    cudaStream_t s2 = 0;
    cudaEvent_t ev0 = 0, ev1 = 0;
    cudaStreamCreateWithFlags(&s2, cudaStreamNonBlocking);
    cudaEventCreateWithFlags(&ev0, cudaEventDisableTiming);
    cudaEventCreateWithFlags(&ev1, cudaEventDisableTiming);
    bool fork_ok = (s2 != 0) && (ev0 != 0) && (ev1 != 0);

    // 1) transpose + bf16-convert all weights (one launch)
    SrcPtrs sp;
    sp.p[0] = query_w;  sp.p[1] = key_w;  sp.p[2] = value_w;
    sp.p[3] = gating_w; sp.p[4] = output_w;
    sp.p[5] = rt_w1;    sp.p[6] = rt_w2;  sp.p[7] = ot_w1; sp.p[8] = ot_w2;
    wt_kernel<<<3024, 256>>>(sp, p_wts);

    // 2) fused input LayerNorms (bf16 outputs)
    ln_fused_kernel<<<T_TOK + 2 * N_RES, 128>>>(resampled, original,
        qn_scale, qn_offset, dn_scale, dn_offset, ot_ln_scale, ot_ln_offset,
        p_qin, p_din, p_ln4);

    // 3) fork: original transition on s2
    cudaStream_t br = 0;
    if (fork_ok) {
        cudaEventRecord(ev0, 0);
        cudaStreamWaitEvent(s2, ev0, 0);
        br = s2;
    }
    gemm_bf<<<dim3(12, 32), 256, gemm_smem, br>>>(p_ln4,
        p_wts + OFF_OT1, p_h2, 1.0f, ot_b1, ACT_RELU, nullptr, 2,
        nullptr, nullptr, 0.0f, nullptr, 0, nullptr, 0,
        N_RES, F_DIM, C_DIM, BIG_HALF);
    gemm_bf<<<dim3(3, 32), 256, gemm_smem, br>>>(p_h2,
        p_wts + OFF_OT2, out_orig, 1.0f, ot_b2, ACT_NONE, original, 0,
        nullptr, nullptr, 0.0f, nullptr, 0, nullptr, 0,
        N_RES, C_DIM, F_DIM, BIG_HALF);
    if (fork_ok) cudaEventRecord(ev1, s2);

    // 4) main chain
    gemm_bf<<<dim3(6, 4), 256, gemm_smem>>>(p_qin,
        p_wts + OFF_QW, p_q, inv_sqrt_kd, nullptr, ACT_NONE, nullptr, 1,
        p_wts + OFF_GW, p_gate, 1.0f, gating_b, ACT_SIGMOID, nullptr, 0,
        T_TOK, C_DIM, C_DIM, 3);
    gemm_bf<<<dim3(6, 32), 256, gemm_smem>>>(p_din,
        p_wts + OFF_KW, p_k, 1.0f, nullptr, ACT_NONE, nullptr, 1,
        p_wts + OFF_VW, p_v, 1.0f, nullptr, ACT_NONE, nullptr, 1,
        N_RES, C_DIM, C_DIM, 3);

    flash_kernel<<<dim3(T_TOK / 64, H_HEADS, RSPLIT), 128, flash_smem>>>(
        p_q, p_k, p_v, attn_mask, p_po, p_pm, p_pl);
    combine_kernel<<<(H_HEADS * T_TOK * KD + 255) / 256, 256>>>(p_po, p_pm, p_pl, p_gate, p_wag);

    gemm_bf<<<dim3(3, 4), 256, gemm_smem>>>(p_wag,
        p_wts + OFF_OW, out_res, 1.0f, output_b, ACT_NONE, resampled, 0,
        nullptr, nullptr, 0.0f, nullptr, 0, nullptr, 0,
        T_TOK, C_DIM, C_DIM, BIG_HALF);

    ln_kernel<<<T_TOK, 128>>>(out_res, rt_ln_scale, rt_ln_offset, p_ln3);
    gemm_bf<<<dim3(12, 4), 256, gemm_smem>>>(p_ln3,
        p_wts + OFF_RT1, p_h1, 1.0f, rt_b1, ACT_RELU, nullptr, 2,
        nullptr, nullptr, 0.0f, nullptr, 0, nullptr, 0,
        T_TOK, F_DIM, C_DIM, BIG_HALF);
    gemm_bf<<<dim3(3, 4), 256, gemm_smem>>>(p_h1,
        p_wts + OFF_RT2, out_res, 1.0f, rt_b2, ACT_NONE, out_res, 0,
        nullptr, nullptr, 0.0f, nullptr, 0, nullptr, 0,
        T_TOK, C_DIM, F_DIM, BIG_HALF);

    // 5) join
    if (fork_ok) cudaStreamWaitEvent(0, ev1, 0);
}